// round 7
// baseline (speedup 1.0000x reference)
#include <cuda_runtime.h>
#include <math.h>

#define BATCH 128
#define LQv   128
#define LAv   512
#define EMBD  300
#define FILT  400
#define EPAD  320
#define KCONV (3 * EPAD)   // 960

// ---- scratch (static __device__: no allocations allowed) ----
__device__ float    g_Q[BATCH * LQv * FILT];
__device__ float    g_A[BATCH * LAv * FILT];
__device__ float    g_T[BATCH * LQv * FILT];
__device__ unsigned g_Bw[KCONV * FILT];
__device__ unsigned g_mq[BATCH * LQv];
__device__ unsigned g_ma[BATCH * LAv];
__device__ float    g_dxy[BATCH * 4];

__device__ __forceinline__ unsigned enc_f(float f) {
    int i = __float_as_int(f);
    return (unsigned)(i ^ ((i >> 31) | 0x80000000));
}
__device__ __forceinline__ float dec_f(unsigned u) {
    int i = (u & 0x80000000u) ? (int)(u ^ 0x80000000u) : ~(int)u;
    return __int_as_float(i);
}
__device__ __forceinline__ unsigned f2tf(float f) {
    unsigned u;
    asm("cvt.rna.tf32.f32 %0, %1;" : "=r"(u) : "f"(f));
    return u;
}
__device__ __forceinline__ void mma8(float* c, const unsigned* a, const unsigned* b) {
    asm("mma.sync.aligned.m16n8k8.row.col.f32.tf32.tf32.f32 "
        "{%0,%1,%2,%3},{%4,%5,%6,%7},{%8,%9},{%0,%1,%2,%3};"
        : "+f"(c[0]), "+f"(c[1]), "+f"(c[2]), "+f"(c[3])
        : "r"(a[0]), "r"(a[1]), "r"(a[2]), "r"(a[3]), "r"(b[0]), "r"(b[1]));
}
__device__ __forceinline__ void cp16(void* sptr, const void* gptr, int bytes) {
    unsigned s = (unsigned)__cvta_generic_to_shared(sptr);
    asm volatile("cp.async.cg.shared.global [%0], [%1], 16, %2;"
                 :: "r"(s), "l"(gptr), "r"(bytes));
}
__device__ __forceinline__ void cp16f(void* sptr, const void* gptr) {
    unsigned s = (unsigned)__cvta_generic_to_shared(sptr);
    asm volatile("cp.async.cg.shared.global [%0], [%1], 16;"
                 :: "r"(s), "l"(gptr));
}
#define CP_COMMIT() asm volatile("cp.async.commit_group;")
#define CP_WAIT1()  asm volatile("cp.async.wait_group 1;")

// ---------------------------------------------------------------------------
// 0) init
// ---------------------------------------------------------------------------
__global__ void init_max_kernel() {
    int idx = blockIdx.x * blockDim.x + threadIdx.x;
    unsigned v = enc_f(-2.0f);
    if (idx < BATCH * LQv) g_mq[idx] = v;
    if (idx < BATCH * LAv) g_ma[idx] = v;
    if (idx < BATCH * 4)   g_dxy[idx] = 0.0f;
}

__global__ void transpose_w_kernel(const float* __restrict__ cw) {
    int idx = blockIdx.x * blockDim.x + threadIdx.x;
    if (idx >= KCONV * FILT) return;
    int kp = idx / FILT, n = idx % FILT;
    int koff = kp / EPAD, e = kp % EPAD;
    float v = (e < EMBD) ? cw[(size_t)n * (EMBD * 3) + e * 3 + koff] : 0.0f;
    g_Bw[idx] = f2tf(v);
}

// ---------------------------------------------------------------------------
// 1) conv encode: block 256 tok x 80 filt, 256 thr (8 warps 4m x 2n, warp 64x40)
//    3-stage cp.async, one barrier per chunk. grid.x: 0 = Q tile, 1..2 = A tiles.
// ---------------------------------------------------------------------------
#define C_KC   32
#define C_NCH  (EPAD / C_KC)       // 10
#define C_ROWS 258
#define E_PITCH 36
#define E_BUF  (C_ROWS * E_PITCH)  // 9288
#define B_PITCH 88
#define B_KOFF (C_KC * B_PITCH)    // 2816
#define B_BUF  (3 * B_KOFF)        // 8448
#define SM_E_OFF 264
#define SM_B_OFF (SM_E_OFF + 3 * E_BUF)
#define SMEM_CONV ((SM_B_OFF + 3 * B_BUF) * 4)   // ~214 KB

__global__ __launch_bounds__(256, 1) void conv_encode_kernel(
    const int* __restrict__ qtok, const int* __restrict__ atok,
    const float* __restrict__ emb, const float* __restrict__ cb)
{
    extern __shared__ unsigned sm[];
    int*      s_tok = (int*)sm;
    unsigned* E     = sm + SM_E_OFF;
    unsigned* Bsm   = sm + SM_B_OFF;

    const int b   = blockIdx.z;
    const int n0  = blockIdx.y * 80;
    const int tid = threadIdx.x;
    const int wid = tid >> 5, lane = tid & 31;
    const int g   = lane >> 2, tig = lane & 3;
    const int wm  = wid & 3,  wn  = wid >> 2;
    const int mwb = wm * 64,  nwb = wn * 40;

    const int* tok;
    float* dst;
    int L, t0;
    if (blockIdx.x == 0) { tok = qtok; dst = g_Q; L = LQv; t0 = 0; }
    else                 { tok = atok; dst = g_A; L = LAv; t0 = (blockIdx.x - 1) * 256; }

    for (int r = tid; r < C_ROWS; r += 256) {
        int tg = t0 + r - 1;
        s_tok[r] = (tg >= 0 && tg < L) ? tok[b * L + tg] : 0;
    }
    __syncthreads();

    auto prefetch = [&](int ch, int bs) {
        int ec = ch * C_KC;
        unsigned* Eb = E + bs * E_BUF;
        unsigned* Bb = Bsm + bs * B_BUF;
        for (int i = tid; i < C_ROWS * 8; i += 256) {
            int r = i >> 3, sg = i & 7;
            int e = ec + sg * 4;
            int el = 300 - e; el = el < 0 ? 0 : (el > 4 ? 4 : el);
            int bytes = el * 4;
            const float* src = emb + (bytes ? ((size_t)s_tok[r] * EMBD + e) : 0);
            cp16(&Eb[r * E_PITCH + sg * 4], src, bytes);
        }
        for (int i = tid; i < 3 * C_KC * 20; i += 256) {
            int ko = i / 640; int r2 = i - ko * 640;
            int kc = r2 / 20; int sg = r2 - kc * 20;
            const unsigned* src = g_Bw + (size_t)(ko * EPAD + ec + kc) * FILT + n0 + sg * 4;
            cp16f(&Bb[ko * B_KOFF + kc * B_PITCH + sg * 4], src);
        }
    };

    float c[4][5][4];
#pragma unroll
    for (int i = 0; i < 4; i++)
#pragma unroll
        for (int j = 0; j < 5; j++)
#pragma unroll
            for (int k = 0; k < 4; k++) c[i][j][k] = 0.0f;

    prefetch(0, 0); CP_COMMIT();
    prefetch(1, 1); CP_COMMIT();

    for (int ch = 0; ch < C_NCH; ch++) {
        int bs = ch % 3;
        CP_WAIT1();
        __syncthreads();
        if (ch + 2 < C_NCH) prefetch(ch + 2, (ch + 2) % 3);
        CP_COMMIT();

        const unsigned* Eb = E + bs * E_BUF;
        const unsigned* Bb = Bsm + bs * B_BUF;

#pragma unroll
        for (int ko = 0; ko < 3; ko++) {
            const unsigned* Bk = Bb + ko * B_KOFF;
#pragma unroll
            for (int kb = 0; kb < C_KC / 8; kb++) {
                int kk = kb * 8;
                unsigned a[4][4];
#pragma unroll
                for (int ms = 0; ms < 4; ms++) {
                    int row = mwb + ms * 16 + g + ko;
                    a[ms][0] = Eb[(row)     * E_PITCH + kk + tig];
                    a[ms][1] = Eb[(row + 8) * E_PITCH + kk + tig];
                    a[ms][2] = Eb[(row)     * E_PITCH + kk + tig + 4];
                    a[ms][3] = Eb[(row + 8) * E_PITCH + kk + tig + 4];
                }
#pragma unroll
                for (int ns = 0; ns < 5; ns++) {
                    unsigned bf[2];
                    int nb = nwb + ns * 8 + g;
                    bf[0] = Bk[(kk + tig)     * B_PITCH + nb];
                    bf[1] = Bk[(kk + tig + 4) * B_PITCH + nb];
#pragma unroll
                    for (int ms = 0; ms < 4; ms++)
                        mma8(c[ms][ns], a[ms], bf);
                }
            }
        }
    }

    // epilogue: + bias, predicated store (Q tile upper half is padding)
#pragma unroll
    for (int ms = 0; ms < 4; ms++) {
#pragma unroll
        for (int ns = 0; ns < 5; ns++) {
            int col = n0 + nwb + ns * 8 + 2 * tig;
            float2 bias = *(const float2*)&cb[col];
            int lr = mwb + ms * 16 + g;
            int grow = t0 + lr;
            if (grow < L)
                *(float2*)&dst[((size_t)b * L + grow) * FILT + col] =
                    make_float2(c[ms][ns][0] + bias.x, c[ms][ns][1] + bias.y);
            if (grow + 8 < L)
                *(float2*)&dst[((size_t)b * L + grow + 8) * FILT + col] =
                    make_float2(c[ms][ns][2] + bias.x, c[ms][ns][3] + bias.y);
        }
    }
}

// ---------------------------------------------------------------------------
// 2) T = Qm @ W : unchanged from R6 (128 thr, warp 64x40, 2-stage)
// ---------------------------------------------------------------------------
#define T_KC 40
#define T_AP 44
#define T_BP 88
#define T_ABUF (128 * T_AP)
#define T_BOFF (2 * T_ABUF)
#define T_BBUF (T_KC * T_BP)
#define SMEM_T ((T_BOFF + 2 * T_BBUF) * 4)

__global__ __launch_bounds__(128, 2) void gemm_T_kernel(const float* __restrict__ W)
{
    extern __shared__ unsigned sm[];
    unsigned* Asm = sm;
    unsigned* Bsm = sm + T_BOFF;

    const int b  = blockIdx.z;
    const int n0 = blockIdx.x * 80;
    const int tid  = threadIdx.x;
    const int wid  = tid >> 5, lane = tid & 31;
    const int g    = lane >> 2, tig = lane & 3;
    const int wm   = wid & 1,  wn  = wid >> 1;
    const int mwb  = wm * 64, nwb = wn * 40;

    const float* Qb = g_Q + (size_t)b * LQv * FILT;

    auto prefetch = [&](int ch, int bs) {
        int k0 = ch * T_KC;
        unsigned* Ab = Asm + bs * T_ABUF;
        unsigned* Bb = Bsm + bs * T_BBUF;
#pragma unroll
        for (int it = 0; it < 10; it++) {
            int i = tid + it * 128;
            int m = i / 10, k4 = i - m * 10;
            cp16f(&Ab[m * T_AP + k4 * 4], Qb + (size_t)m * FILT + k0 + k4 * 4);
        }
        for (int i = tid; i < T_KC * 20; i += 128) {
            int kc = i / 20, sg = i - kc * 20;
            cp16f(&Bb[kc * T_BP + sg * 4], W + (size_t)(k0 + kc) * FILT + n0 + sg * 4);
        }
    };

    float c[4][5][4];
#pragma unroll
    for (int i = 0; i < 4; i++)
#pragma unroll
        for (int j = 0; j < 5; j++)
#pragma unroll
            for (int k = 0; k < 4; k++) c[i][j][k] = 0.0f;

    prefetch(0, 0);
    CP_COMMIT();

    for (int ch = 0; ch < FILT / T_KC; ch++) {
        int bs = ch & 1;
        if (ch + 1 < FILT / T_KC) prefetch(ch + 1, bs ^ 1);
        CP_COMMIT();
        CP_WAIT1();
        __syncthreads();

        const unsigned* Ab = Asm + bs * T_ABUF;
        const unsigned* Bb = Bsm + bs * T_BBUF;

#pragma unroll
        for (int kb = 0; kb < T_KC / 8; kb++) {
            int kk = kb * 8;
            unsigned a[4][4];
#pragma unroll
            for (int ms = 0; ms < 4; ms++) {
                int row = mwb + ms * 16 + g;
                a[ms][0] = Ab[(row)     * T_AP + kk + tig];
                a[ms][1] = Ab[(row + 8) * T_AP + kk + tig];
                a[ms][2] = Ab[(row)     * T_AP + kk + tig + 4];
                a[ms][3] = Ab[(row + 8) * T_AP + kk + tig + 4];
            }
#pragma unroll
            for (int ns = 0; ns < 5; ns++) {
                unsigned bf[2];
                int nb = nwb + ns * 8 + g;
                bf[0] = Bb[(kk + tig)     * T_BP + nb];
                bf[1] = Bb[(kk + tig + 4) * T_BP + nb];
#pragma unroll
                for (int ms = 0; ms < 4; ms++)
                    mma8(c[ms][ns], a[ms], bf);
            }
        }
        __syncthreads();
    }

#pragma unroll
    for (int ms = 0; ms < 4; ms++) {
#pragma unroll
        for (int ns = 0; ns < 5; ns++) {
            int col = n0 + nwb + ns * 8 + 2 * tig;
            int row0 = mwb + ms * 16 + g;
            *(float2*)&g_T[((size_t)b * LQv + row0) * FILT + col] =
                make_float2(c[ms][ns][0], c[ms][ns][1]);
            *(float2*)&g_T[((size_t)b * LQv + row0 + 8) * FILT + col] =
                make_float2(c[ms][ns][2], c[ms][ns][3]);
        }
    }
}

// ---------------------------------------------------------------------------
// 3) G = tanh(T @ A^T) fused maxes. Block 128q x 256a, 256 thr (2m x 4n, warp 64x64).
//    3-stage cp.async, one barrier per chunk. grid (2 a-tiles, 128 b).
// ---------------------------------------------------------------------------
#define G_KC 40
#define G_AP 44
#define G_ABUF (128 * G_AP)            // 5632
#define G_BOFF (3 * G_ABUF)            // 16896
#define G_BBUF (256 * G_AP)            // 11264
#define G_RED  (G_BOFF + 3 * G_BBUF)   // 50688
#define SMEM_G ((G_RED + 384) * 4)     // ~204 KB

__global__ __launch_bounds__(256, 1) void gemm_G_kernel()
{
    extern __shared__ unsigned sm[];
    unsigned* Asm  = sm;
    unsigned* Bsm  = sm + G_BOFF;
    unsigned* srow = sm + G_RED;        // 128
    unsigned* scol = sm + G_RED + 128;  // 256

    const int b  = blockIdx.y;
    const int a0 = blockIdx.x * 256;
    const int tid  = threadIdx.x;
    const int wid  = tid >> 5, lane = tid & 31;
    const int g    = lane >> 2, tig = lane & 3;
    const int wm   = wid & 1,  wn  = wid >> 1;
    const int mwb  = wm * 64, nwb = wn * 64;

    if (tid < 128) srow[tid] = enc_f(-2.0f);
    scol[tid] = enc_f(-2.0f);

    const float* Tb  = g_T + (size_t)b * LQv * FILT;
    const float* Ab0 = g_A + ((size_t)b * LAv + a0) * FILT;

    auto prefetch = [&](int ch, int bs) {
        int k0 = ch * G_KC;
        unsigned* Abuf = Asm + bs * G_ABUF;
        unsigned* Bbuf = Bsm + bs * G_BBUF;
#pragma unroll
        for (int it = 0; it < 5; it++) {
            int i = tid + it * 256;                  // 1280 = 128 q x 10 k4
            int m = i / 10, k4 = i - m * 10;
            cp16f(&Abuf[m * G_AP + k4 * 4], Tb + (size_t)m * FILT + k0 + k4 * 4);
        }
#pragma unroll
        for (int it = 0; it < 10; it++) {
            int i = tid + it * 256;                  // 2560 = 256 a x 10 k4
            int n = i / 10, k4 = i - n * 10;
            cp16f(&Bbuf[n * G_AP + k4 * 4], Ab0 + (size_t)n * FILT + k0 + k4 * 4);
        }
    };

    float c[4][8][4];
#pragma unroll
    for (int i = 0; i < 4; i++)
#pragma unroll
        for (int j = 0; j < 8; j++)
#pragma unroll
            for (int k = 0; k < 4; k++) c[i][j][k] = 0.0f;

    prefetch(0, 0); CP_COMMIT();
    prefetch(1, 1); CP_COMMIT();

    for (int ch = 0; ch < FILT / G_KC; ch++) {
        int bs = ch % 3;
        CP_WAIT1();
        __syncthreads();
        if (ch + 2 < FILT / G_KC) prefetch(ch + 2, (ch + 2) % 3);
        CP_COMMIT();

        const unsigned* Abuf = Asm + bs * G_ABUF;
        const unsigned* Bbuf = Bsm + bs * G_BBUF;

#pragma unroll
        for (int kb = 0; kb < G_KC / 8; kb++) {
            int kk = kb * 8;
            unsigned a[4][4];
#pragma unroll
            for (int ms = 0; ms < 4; ms++) {
                int row = mwb + ms * 16 + g;
                a[ms][0] = Abuf[(row)     * G_AP + kk + tig];
                a[ms][1] = Abuf[(row + 8) * G_AP + kk + tig];
                a[ms][2] = Abuf[(row)     * G_AP + kk + tig + 4];
                a[ms][3] = Abuf[(row + 8) * G_AP + kk + tig + 4];
            }
#pragma unroll
            for (int ns = 0; ns < 8; ns++) {
                unsigned bf[2];
                int nb = nwb + ns * 8 + g;
                bf[0] = Bbuf[nb * G_AP + kk + tig];
                bf[1] = Bbuf[nb * G_AP + kk + tig + 4];
#pragma unroll
                for (int ms = 0; ms < 4; ms++)
                    mma8(c[ms][ns], a[ms], bf);
            }
        }
    }

    // tanh + row/col maxes
#pragma unroll
    for (int ms = 0; ms < 4; ms++) {
        float r0 = -2.0f, r1 = -2.0f;
#pragma unroll
        for (int ns = 0; ns < 8; ns++) {
#pragma unroll
            for (int k = 0; k < 4; k++) c[ms][ns][k] = tanhf(c[ms][ns][k]);
            r0 = fmaxf(r0, fmaxf(c[ms][ns][0], c[ms][ns][1]));
            r1 = fmaxf(r1, fmaxf(c[ms][ns][2], c[ms][ns][3]));
        }
        atomicMax(&srow[mwb + ms * 16 + g],     enc_f(r0));
        atomicMax(&srow[mwb + ms * 16 + g + 8], enc_f(r1));
    }
#pragma unroll
    for (int ns = 0; ns < 8; ns++) {
        float c0 = -2.0f, c1 = -2.0f;
#pragma unroll
        for (int ms = 0; ms < 4; ms++) {
            c0 = fmaxf(c0, fmaxf(c[ms][ns][0], c[ms][ns][2]));
            c1 = fmaxf(c1, fmaxf(c[ms][ns][1], c[ms][ns][3]));
        }
        int nb = nwb + ns * 8 + 2 * tig;
        atomicMax(&scol[nb],     enc_f(c0));
        atomicMax(&scol[nb + 1], enc_f(c1));
    }
    __syncthreads();

    if (tid < 128) atomicMax(&g_mq[b * LQv + tid], srow[tid]);
    atomicMax(&g_ma[b * LAv + a0 + tid], scol[tid]);
}

// ---------------------------------------------------------------------------
// 4a) per-batch softmax over maxes; writes normalized weights (float bits)
//     back into g_mq / g_ma
// ---------------------------------------------------------------------------
__device__ __forceinline__ float warp_max(float v) {
#pragma unroll
    for (int o = 16; o > 0; o >>= 1) v = fmaxf(v, __shfl_xor_sync(0xffffffffu, v, o));
    return v;
}
__device__ __forceinline__ float warp_sum(float v) {
#pragma unroll
    for (int o = 16; o > 0; o >>= 1) v += __shfl_xor_sync(0xffffffffu, v, o);
    return v;
}

__global__ __launch_bounds__(256) void softmax_kernel()
{
    __shared__ float sq[LQv], sa[LAv];
    __shared__ float smax[2], ssum[2];

    const int b = blockIdx.x;
    const int tid = threadIdx.x;
    const int lane = tid & 31;

    for (int q = tid; q < LQv; q += 256) sq[q] = dec_f(g_mq[b * LQv + q]);
    for (int a = tid; a < LAv; a += 256) sa[a] = dec_f(g_ma[b * LAv + a]);
    __syncthreads();

    if (tid < 32) {
        float m = -1e30f;
        for (int q = lane; q < LQv; q += 32) m = fmaxf(m, sq[q]);
        m = warp_max(m);
        if (lane == 0) smax[0] = m;
    } else if (tid < 64) {
        float m = -1e30f;
        for (int a = lane; a < LAv; a += 32) m = fmaxf(m, sa[a]);
        m = warp_max(m);
        if (lane == 0) smax[1] = m;
    }
    __syncthreads();
    for (int q = tid; q < LQv; q += 256) sq[q] = expf(sq[q] - smax[0]);
    for (int a = tid; a < LAv; a += 256) sa[a] = expf(sa[a] - smax[1]);
    __syncthreads();
    if (tid < 32) {
        float s = 0.0f;
        for (int q = lane; q < LQv; q += 32) s += sq[q];
        s = warp_sum(s);
        if (lane == 0) ssum[0] = s;
    } else if (tid < 64) {
        float s = 0.0f;
        for (int a = lane; a < LAv; a += 32) s += sa[a];
        s = warp_sum(s);
        if (lane == 0) ssum[1] = s;
    }
    __syncthreads();
    float invq = 1.0f / ssum[0], inva = 1.0f / ssum[1];
    for (int q = tid; q < LQv; q += 256)
        g_mq[b * LQv + q] = __float_as_uint(sq[q] * invq);
    for (int a = tid; a < LAv; a += 256)
        g_ma[b * LAv + a] = __float_as_uint(sa[a] * inva);
}

// ---------------------------------------------------------------------------
// 4b) pooling partials: grid (128 b, 2 halves), 256 thr, 200 f each
// ---------------------------------------------------------------------------
__global__ __launch_bounds__(256) void pool_kernel()
{
    __shared__ float wq[LQv], wa[LAv];
    __shared__ float rd[256], rx[256], ry[256];

    const int b = blockIdx.x;
    const int f0 = blockIdx.y * 200;
    const int tid = threadIdx.x;

    for (int q = tid; q < LQv; q += 256) wq[q] = __uint_as_float(g_mq[b * LQv + q]);
    for (int a = tid; a < LAv; a += 256) wa[a] = __uint_as_float(g_ma[b * LAv + a]);
    __syncthreads();

    float d = 0.0f, x = 0.0f, y = 0.0f;
    if (tid < 200) {
        int f = f0 + tid;
        const float* qp = g_Q + (size_t)b * LQv * FILT + f;
        float accq = 0.0f;
#pragma unroll 8
        for (int q = 0; q < LQv; q++) accq += qp[(size_t)q * FILT] * wq[q];
        const float* ap = g_A + (size_t)b * LAv * FILT + f;
        float acca = 0.0f;
#pragma unroll 8
        for (int a = 0; a < LAv; a++) acca += ap[(size_t)a * FILT] * wa[a];
        d = accq * acca; x = accq * accq; y = acca * acca;
    }
    rd[tid] = d; rx[tid] = x; ry[tid] = y;
    __syncthreads();
#pragma unroll
    for (int s = 128; s > 0; s >>= 1) {
        if (tid < s) {
            rd[tid] += rd[tid + s];
            rx[tid] += rx[tid + s];
            ry[tid] += ry[tid + s];
        }
        __syncthreads();
    }
    if (tid == 0) {
        atomicAdd(&g_dxy[b * 4 + 0], rd[0]);
        atomicAdd(&g_dxy[b * 4 + 1], rx[0]);
        atomicAdd(&g_dxy[b * 4 + 2], ry[0]);
    }
}

// ---------------------------------------------------------------------------
// 4c) final cosine
// ---------------------------------------------------------------------------
__global__ __launch_bounds__(128) void final_out_kernel(float* __restrict__ out)
{
    int b = threadIdx.x;
    float D = g_dxy[b * 4 + 0];
    float X = g_dxy[b * 4 + 1];
    float Y = g_dxy[b * 4 + 2];
    float nq = fmaxf(sqrtf(X), 1e-8f);
    float na = fmaxf(sqrtf(Y), 1e-8f);
    out[b] = D / (nq * na);
}

// ---------------------------------------------------------------------------
// launch
// ---------------------------------------------------------------------------
extern "C" void kernel_launch(void* const* d_in, const int* in_sizes, int n_in,
                              void* d_out, int out_size)
{
    const int*   questions = (const int*)d_in[0];
    const int*   answers   = (const int*)d_in[1];
    const float* emb       = (const float*)d_in[2];
    const float* conv_w    = (const float*)d_in[3];
    const float* conv_b    = (const float*)d_in[4];
    const float* W         = (const float*)d_in[5];
    float*       out       = (float*)d_out;

    (void)in_sizes; (void)n_in; (void)out_size;

    static bool attr_done = false;
    if (!attr_done) {
        cudaFuncSetAttribute(conv_encode_kernel,
                             cudaFuncAttributeMaxDynamicSharedMemorySize, SMEM_CONV);
        cudaFuncSetAttribute(gemm_T_kernel,
                             cudaFuncAttributeMaxDynamicSharedMemorySize, SMEM_T);
        cudaFuncSetAttribute(gemm_G_kernel,
                             cudaFuncAttributeMaxDynamicSharedMemorySize, SMEM_G);
        attr_done = true;
    }

    init_max_kernel<<<(BATCH * LAv + 255) / 256, 256>>>();
    transpose_w_kernel<<<(KCONV * FILT + 255) / 256, 256>>>(conv_w);

    conv_encode_kernel<<<dim3(3, FILT / 80, BATCH), 256, SMEM_CONV>>>(
        questions, answers, emb, conv_b);

    gemm_T_kernel<<<dim3(FILT / 80, 1, BATCH), 128, SMEM_T>>>(W);
    gemm_G_kernel<<<dim3(2, BATCH), 256, SMEM_G>>>();

    softmax_kernel<<<BATCH, 256>>>();
    pool_kernel<<<dim3(BATCH, 2), 256>>>();
    final_out_kernel<<<1, 128>>>(out);
}

// round 8
// speedup vs baseline: 1.1923x; 1.1923x over previous
#include <cuda_runtime.h>
#include <math.h>

#define BATCH 128
#define LQv   128
#define LAv   512
#define EMBD  300
#define FILT  400
#define EPAD  320
#define KCONV (3 * EPAD)   // 960

// ---- scratch (static __device__: no allocations allowed) ----
__device__ float    g_Q[BATCH * LQv * FILT];
__device__ float    g_A[BATCH * LAv * FILT];
__device__ float    g_T[BATCH * LQv * FILT];
__device__ unsigned g_Bw[KCONV * FILT];
__device__ unsigned g_mq[BATCH * LQv];
__device__ unsigned g_ma[BATCH * LAv];
__device__ float    g_dxy[BATCH * 4];

__device__ __forceinline__ unsigned enc_f(float f) {
    int i = __float_as_int(f);
    return (unsigned)(i ^ ((i >> 31) | 0x80000000));
}
__device__ __forceinline__ float dec_f(unsigned u) {
    int i = (u & 0x80000000u) ? (int)(u ^ 0x80000000u) : ~(int)u;
    return __int_as_float(i);
}
__device__ __forceinline__ unsigned f2tf(float f) {
    unsigned u;
    asm("cvt.rna.tf32.f32 %0, %1;" : "=r"(u) : "f"(f));
    return u;
}
__device__ __forceinline__ void mma8(float* c, const unsigned* a, const unsigned* b) {
    asm("mma.sync.aligned.m16n8k8.row.col.f32.tf32.tf32.f32 "
        "{%0,%1,%2,%3},{%4,%5,%6,%7},{%8,%9},{%0,%1,%2,%3};"
        : "+f"(c[0]), "+f"(c[1]), "+f"(c[2]), "+f"(c[3])
        : "r"(a[0]), "r"(a[1]), "r"(a[2]), "r"(a[3]), "r"(b[0]), "r"(b[1]));
}
__device__ __forceinline__ void cp16(void* sptr, const void* gptr, int bytes) {
    unsigned s = (unsigned)__cvta_generic_to_shared(sptr);
    asm volatile("cp.async.cg.shared.global [%0], [%1], 16, %2;"
                 :: "r"(s), "l"(gptr), "r"(bytes));
}
__device__ __forceinline__ void cp16f(void* sptr, const void* gptr) {
    unsigned s = (unsigned)__cvta_generic_to_shared(sptr);
    asm volatile("cp.async.cg.shared.global [%0], [%1], 16;"
                 :: "r"(s), "l"(gptr));
}
#define CP_COMMIT() asm volatile("cp.async.commit_group;")
#define CP_WAIT1()  asm volatile("cp.async.wait_group 1;")

// ---------------------------------------------------------------------------
// 0) init
// ---------------------------------------------------------------------------
__global__ void init_max_kernel() {
    int idx = blockIdx.x * blockDim.x + threadIdx.x;
    unsigned v = enc_f(-2.0f);
    if (idx < BATCH * LQv) g_mq[idx] = v;
    if (idx < BATCH * LAv) g_ma[idx] = v;
    if (idx < BATCH * 4)   g_dxy[idx] = 0.0f;
}

__global__ void transpose_w_kernel(const float* __restrict__ cw) {
    int idx = blockIdx.x * blockDim.x + threadIdx.x;
    if (idx >= KCONV * FILT) return;
    int kp = idx / FILT, n = idx % FILT;
    int koff = kp / EPAD, e = kp % EPAD;
    float v = (e < EMBD) ? cw[(size_t)n * (EMBD * 3) + e * 3 + koff] : 0.0f;
    g_Bw[idx] = f2tf(v);
}

// ---------------------------------------------------------------------------
// 1) conv encode (R5 config): 128 thr, 4 warps (2m x 2n), warp 64x40,
//    block 128 tok x 80 filt, 2-stage cp.async, 2 CTAs/SM.
//    is_q selects Q (L=128) or A (L=512); t0 = blockIdx.x * 128.
// ---------------------------------------------------------------------------
#define C_KC 32
#define C_NCH (EPAD / C_KC)     // 10
#define E_PITCH 36
#define E_BUF  (130 * E_PITCH)
#define B_PITCH 88
#define B_KOFF (C_KC * B_PITCH)
#define B_BUF  (3 * B_KOFF)
#define SM_E_OFF 136
#define SM_B_OFF (SM_E_OFF + 2 * E_BUF)
#define SMEM_CONV ((SM_B_OFF + 2 * B_BUF) * 4)

__global__ __launch_bounds__(128, 2) void conv_encode_kernel(
    const int* __restrict__ qtok, const int* __restrict__ atok,
    const float* __restrict__ emb, const float* __restrict__ cb, int is_q)
{
    extern __shared__ unsigned sm[];
    int*      s_tok = (int*)sm;
    unsigned* E     = sm + SM_E_OFF;
    unsigned* Bsm   = sm + SM_B_OFF;

    const int b   = blockIdx.z;
    const int n0  = blockIdx.y * 80;
    const int tid = threadIdx.x;
    const int wid = tid >> 5, lane = tid & 31;
    const int g   = lane >> 2, tig = lane & 3;
    const int wm  = wid & 1,  wn  = wid >> 1;
    const int mwb = wm * 64,  nwb = wn * 40;

    const int* tok = is_q ? qtok : atok;
    float* dst     = is_q ? g_Q : g_A;
    const int L    = is_q ? LQv : LAv;
    const int t0   = blockIdx.x * 128;

    for (int r = tid; r < 130; r += 128) {
        int tg = t0 + r - 1;
        s_tok[r] = (tg >= 0 && tg < L) ? tok[b * L + tg] : 0;
    }
    __syncthreads();

    auto prefetch = [&](int ch, int bs) {
        int ec = ch * C_KC;
        unsigned* Eb = E + bs * E_BUF;
        unsigned* Bb = Bsm + bs * B_BUF;
        for (int i = tid; i < 130 * 8; i += 128) {
            int r = i >> 3, sg = i & 7;
            int e = ec + sg * 4;
            int el = 300 - e; el = el < 0 ? 0 : (el > 4 ? 4 : el);
            int bytes = el * 4;
            const float* src = emb + (bytes ? ((size_t)s_tok[r] * EMBD + e) : 0);
            cp16(&Eb[r * E_PITCH + sg * 4], src, bytes);
        }
        for (int i = tid; i < 3 * C_KC * 20; i += 128) {
            int ko = i / 640; int r2 = i - ko * 640;
            int kc = r2 / 20; int sg = r2 - kc * 20;
            const unsigned* src = g_Bw + (size_t)(ko * EPAD + ec + kc) * FILT + n0 + sg * 4;
            cp16f(&Bb[ko * B_KOFF + kc * B_PITCH + sg * 4], src);
        }
    };

    float c[4][5][4];
#pragma unroll
    for (int i = 0; i < 4; i++)
#pragma unroll
        for (int j = 0; j < 5; j++)
#pragma unroll
            for (int k = 0; k < 4; k++) c[i][j][k] = 0.0f;

    prefetch(0, 0);
    CP_COMMIT();

    for (int ch = 0; ch < C_NCH; ch++) {
        int bs = ch & 1;
        if (ch + 1 < C_NCH) prefetch(ch + 1, bs ^ 1);
        CP_COMMIT();
        CP_WAIT1();
        __syncthreads();

        const unsigned* Eb = E + bs * E_BUF;
        const unsigned* Bb = Bsm + bs * B_BUF;

#pragma unroll
        for (int ko = 0; ko < 3; ko++) {
            const unsigned* Bk = Bb + ko * B_KOFF;
#pragma unroll
            for (int kb = 0; kb < C_KC / 8; kb++) {
                int kk = kb * 8;
                unsigned a[4][4];
#pragma unroll
                for (int ms = 0; ms < 4; ms++) {
                    int row = mwb + ms * 16 + g + ko;
                    a[ms][0] = Eb[(row)     * E_PITCH + kk + tig];
                    a[ms][1] = Eb[(row + 8) * E_PITCH + kk + tig];
                    a[ms][2] = Eb[(row)     * E_PITCH + kk + tig + 4];
                    a[ms][3] = Eb[(row + 8) * E_PITCH + kk + tig + 4];
                }
#pragma unroll
                for (int ns = 0; ns < 5; ns++) {
                    unsigned bf[2];
                    int nb = nwb + ns * 8 + g;
                    bf[0] = Bk[(kk + tig)     * B_PITCH + nb];
                    bf[1] = Bk[(kk + tig + 4) * B_PITCH + nb];
#pragma unroll
                    for (int ms = 0; ms < 4; ms++)
                        mma8(c[ms][ns], a[ms], bf);
                }
            }
        }
        __syncthreads();
    }

#pragma unroll
    for (int ms = 0; ms < 4; ms++) {
#pragma unroll
        for (int ns = 0; ns < 5; ns++) {
            int col = n0 + nwb + ns * 8 + 2 * tig;
            float2 bias = *(const float2*)&cb[col];
            int row0 = t0 + mwb + ms * 16 + g;
            *(float2*)&dst[((size_t)b * L + row0) * FILT + col] =
                make_float2(c[ms][ns][0] + bias.x, c[ms][ns][1] + bias.y);
            *(float2*)&dst[((size_t)b * L + row0 + 8) * FILT + col] =
                make_float2(c[ms][ns][2] + bias.x, c[ms][ns][3] + bias.y);
        }
    }
}

// ---------------------------------------------------------------------------
// 2) T = Qm @ W : 128 thr, warp 64x40, 2-stage (R5 config)
// ---------------------------------------------------------------------------
#define T_KC 40
#define T_AP 44
#define T_BP 88
#define T_ABUF (128 * T_AP)
#define T_BOFF (2 * T_ABUF)
#define T_BBUF (T_KC * T_BP)
#define SMEM_T ((T_BOFF + 2 * T_BBUF) * 4)

__global__ __launch_bounds__(128, 2) void gemm_T_kernel(const float* __restrict__ W)
{
    extern __shared__ unsigned sm[];
    unsigned* Asm = sm;
    unsigned* Bsm = sm + T_BOFF;

    const int b  = blockIdx.z;
    const int n0 = blockIdx.x * 80;
    const int tid  = threadIdx.x;
    const int wid  = tid >> 5, lane = tid & 31;
    const int g    = lane >> 2, tig = lane & 3;
    const int wm   = wid & 1,  wn  = wid >> 1;
    const int mwb  = wm * 64, nwb = wn * 40;

    const float* Qb = g_Q + (size_t)b * LQv * FILT;

    auto prefetch = [&](int ch, int bs) {
        int k0 = ch * T_KC;
        unsigned* Ab = Asm + bs * T_ABUF;
        unsigned* Bb = Bsm + bs * T_BBUF;
#pragma unroll
        for (int it = 0; it < 10; it++) {
            int i = tid + it * 128;
            int m = i / 10, k4 = i - m * 10;
            cp16f(&Ab[m * T_AP + k4 * 4], Qb + (size_t)m * FILT + k0 + k4 * 4);
        }
        for (int i = tid; i < T_KC * 20; i += 128) {
            int kc = i / 20, sg = i - kc * 20;
            cp16f(&Bb[kc * T_BP + sg * 4], W + (size_t)(k0 + kc) * FILT + n0 + sg * 4);
        }
    };

    float c[4][5][4];
#pragma unroll
    for (int i = 0; i < 4; i++)
#pragma unroll
        for (int j = 0; j < 5; j++)
#pragma unroll
            for (int k = 0; k < 4; k++) c[i][j][k] = 0.0f;

    prefetch(0, 0);
    CP_COMMIT();

    for (int ch = 0; ch < FILT / T_KC; ch++) {
        int bs = ch & 1;
        if (ch + 1 < FILT / T_KC) prefetch(ch + 1, bs ^ 1);
        CP_COMMIT();
        CP_WAIT1();
        __syncthreads();

        const unsigned* Ab = Asm + bs * T_ABUF;
        const unsigned* Bb = Bsm + bs * T_BBUF;

#pragma unroll
        for (int kb = 0; kb < T_KC / 8; kb++) {
            int kk = kb * 8;
            unsigned a[4][4];
#pragma unroll
            for (int ms = 0; ms < 4; ms++) {
                int row = mwb + ms * 16 + g;
                a[ms][0] = Ab[(row)     * T_AP + kk + tig];
                a[ms][1] = Ab[(row + 8) * T_AP + kk + tig];
                a[ms][2] = Ab[(row)     * T_AP + kk + tig + 4];
                a[ms][3] = Ab[(row + 8) * T_AP + kk + tig + 4];
            }
#pragma unroll
            for (int ns = 0; ns < 5; ns++) {
                unsigned bf[2];
                int nb = nwb + ns * 8 + g;
                bf[0] = Bb[(kk + tig)     * T_BP + nb];
                bf[1] = Bb[(kk + tig + 4) * T_BP + nb];
#pragma unroll
                for (int ms = 0; ms < 4; ms++)
                    mma8(c[ms][ns], a[ms], bf);
            }
        }
        __syncthreads();
    }

#pragma unroll
    for (int ms = 0; ms < 4; ms++) {
#pragma unroll
        for (int ns = 0; ns < 5; ns++) {
            int col = n0 + nwb + ns * 8 + 2 * tig;
            int row0 = mwb + ms * 16 + g;
            *(float2*)&g_T[((size_t)b * LQv + row0) * FILT + col] =
                make_float2(c[ms][ns][0], c[ms][ns][1]);
            *(float2*)&g_T[((size_t)b * LQv + row0 + 8) * FILT + col] =
                make_float2(c[ms][ns][2], c[ms][ns][3]);
        }
    }
}

// ---------------------------------------------------------------------------
// 3) G = tanh(T @ A^T) fused maxes (R5 config): 256 thr, 8 warps (2m x 4n),
//    warp 64x32, block 128 x 128, 2-stage, 2 CTAs/SM.
// ---------------------------------------------------------------------------
#define G_KC 40
#define G_AP 44
#define G_ABUF (128 * G_AP)
#define G_BOFF (2 * G_ABUF)
#define G_BBUF (128 * G_AP)
#define G_RED  (G_BOFF + 2 * G_BBUF)
#define SMEM_G ((G_RED + 256) * 4)

__global__ __launch_bounds__(256, 2) void gemm_G_kernel()
{
    extern __shared__ unsigned sm[];
    unsigned* Asm  = sm;
    unsigned* Bsm  = sm + G_BOFF;
    unsigned* srow = sm + G_RED;
    unsigned* scol = sm + G_RED + 128;

    const int b  = blockIdx.y;
    const int a0 = blockIdx.x * 128;
    const int tid  = threadIdx.x;
    const int wid  = tid >> 5, lane = tid & 31;
    const int g    = lane >> 2, tig = lane & 3;
    const int wm   = wid & 1,  wn  = wid >> 1;
    const int mwb  = wm * 64, nwb = wn * 32;

    if (tid < 128) { srow[tid] = enc_f(-2.0f); scol[tid] = enc_f(-2.0f); }

    const float* Tb  = g_T + (size_t)b * LQv * FILT;
    const float* Ab0 = g_A + ((size_t)b * LAv + a0) * FILT;

    auto prefetch = [&](int ch, int bs) {
        int k0 = ch * G_KC;
        unsigned* Abuf = Asm + bs * G_ABUF;
        unsigned* Bbuf = Bsm + bs * G_BBUF;
#pragma unroll
        for (int it = 0; it < 5; it++) {
            int i = tid + it * 256;
            int m = i / 10, k4 = i - m * 10;
            cp16f(&Abuf[m * G_AP + k4 * 4], Tb + (size_t)m * FILT + k0 + k4 * 4);
        }
#pragma unroll
        for (int it = 0; it < 5; it++) {
            int i = tid + it * 256;
            int n = i / 10, k4 = i - n * 10;
            cp16f(&Bbuf[n * G_AP + k4 * 4], Ab0 + (size_t)n * FILT + k0 + k4 * 4);
        }
    };

    float c[4][4][4];
#pragma unroll
    for (int i = 0; i < 4; i++)
#pragma unroll
        for (int j = 0; j < 4; j++)
#pragma unroll
            for (int k = 0; k < 4; k++) c[i][j][k] = 0.0f;

    prefetch(0, 0);
    CP_COMMIT();

    for (int ch = 0; ch < FILT / G_KC; ch++) {
        int bs = ch & 1;
        if (ch + 1 < FILT / G_KC) prefetch(ch + 1, bs ^ 1);
        CP_COMMIT();
        CP_WAIT1();
        __syncthreads();

        const unsigned* Abuf = Asm + bs * G_ABUF;
        const unsigned* Bbuf = Bsm + bs * G_BBUF;

#pragma unroll
        for (int kb = 0; kb < G_KC / 8; kb++) {
            int kk = kb * 8;
            unsigned a[4][4];
#pragma unroll
            for (int ms = 0; ms < 4; ms++) {
                int row = mwb + ms * 16 + g;
                a[ms][0] = Abuf[(row)     * G_AP + kk + tig];
                a[ms][1] = Abuf[(row + 8) * G_AP + kk + tig];
                a[ms][2] = Abuf[(row)     * G_AP + kk + tig + 4];
                a[ms][3] = Abuf[(row + 8) * G_AP + kk + tig + 4];
            }
#pragma unroll
            for (int ns = 0; ns < 4; ns++) {
                unsigned bf[2];
                int nb = nwb + ns * 8 + g;
                bf[0] = Bbuf[nb * G_AP + kk + tig];
                bf[1] = Bbuf[nb * G_AP + kk + tig + 4];
#pragma unroll
                for (int ms = 0; ms < 4; ms++)
                    mma8(c[ms][ns], a[ms], bf);
            }
        }
        __syncthreads();
    }

#pragma unroll
    for (int ms = 0; ms < 4; ms++) {
        float r0 = -2.0f, r1 = -2.0f;
#pragma unroll
        for (int ns = 0; ns < 4; ns++) {
#pragma unroll
            for (int k = 0; k < 4; k++) c[ms][ns][k] = tanhf(c[ms][ns][k]);
            r0 = fmaxf(r0, fmaxf(c[ms][ns][0], c[ms][ns][1]));
            r1 = fmaxf(r1, fmaxf(c[ms][ns][2], c[ms][ns][3]));
        }
        atomicMax(&srow[mwb + ms * 16 + g],     enc_f(r0));
        atomicMax(&srow[mwb + ms * 16 + g + 8], enc_f(r1));
    }
#pragma unroll
    for (int ns = 0; ns < 4; ns++) {
        float c0 = -2.0f, c1 = -2.0f;
#pragma unroll
        for (int ms = 0; ms < 4; ms++) {
            c0 = fmaxf(c0, fmaxf(c[ms][ns][0], c[ms][ns][2]));
            c1 = fmaxf(c1, fmaxf(c[ms][ns][1], c[ms][ns][3]));
        }
        int nb = nwb + ns * 8 + 2 * tig;
        atomicMax(&scol[nb],     enc_f(c0));
        atomicMax(&scol[nb + 1], enc_f(c1));
    }
    __syncthreads();

    if (tid < 128) {
        atomicMax(&g_mq[b * LQv + tid], srow[tid]);
        atomicMax(&g_ma[b * LAv + a0 + tid], scol[tid]);
    }
}

// ---------------------------------------------------------------------------
// 4a) per-batch softmax; writes normalized weights back into g_mq / g_ma
// ---------------------------------------------------------------------------
__device__ __forceinline__ float warp_max(float v) {
#pragma unroll
    for (int o = 16; o > 0; o >>= 1) v = fmaxf(v, __shfl_xor_sync(0xffffffffu, v, o));
    return v;
}
__device__ __forceinline__ float warp_sum(float v) {
#pragma unroll
    for (int o = 16; o > 0; o >>= 1) v += __shfl_xor_sync(0xffffffffu, v, o);
    return v;
}

__global__ __launch_bounds__(256) void softmax_kernel()
{
    __shared__ float sq[LQv], sa[LAv];
    __shared__ float smax[2], ssum[2];

    const int b = blockIdx.x;
    const int tid = threadIdx.x;
    const int lane = tid & 31;

    for (int q = tid; q < LQv; q += 256) sq[q] = dec_f(g_mq[b * LQv + q]);
    for (int a = tid; a < LAv; a += 256) sa[a] = dec_f(g_ma[b * LAv + a]);
    __syncthreads();

    if (tid < 32) {
        float m = -1e30f;
        for (int q = lane; q < LQv; q += 32) m = fmaxf(m, sq[q]);
        m = warp_max(m);
        if (lane == 0) smax[0] = m;
    } else if (tid < 64) {
        float m = -1e30f;
        for (int a = lane; a < LAv; a += 32) m = fmaxf(m, sa[a]);
        m = warp_max(m);
        if (lane == 0) smax[1] = m;
    }
    __syncthreads();
    for (int q = tid; q < LQv; q += 256) sq[q] = expf(sq[q] - smax[0]);
    for (int a = tid; a < LAv; a += 256) sa[a] = expf(sa[a] - smax[1]);
    __syncthreads();
    if (tid < 32) {
        float s = 0.0f;
        for (int q = lane; q < LQv; q += 32) s += sq[q];
        s = warp_sum(s);
        if (lane == 0) ssum[0] = s;
    } else if (tid < 64) {
        float s = 0.0f;
        for (int a = lane; a < LAv; a += 32) s += sa[a];
        s = warp_sum(s);
        if (lane == 0) ssum[1] = s;
    }
    __syncthreads();
    float invq = 1.0f / ssum[0], inva = 1.0f / ssum[1];
    for (int q = tid; q < LQv; q += 256)
        g_mq[b * LQv + q] = __float_as_uint(sq[q] * invq);
    for (int a = tid; a < LAv; a += 256)
        g_ma[b * LAv + a] = __float_as_uint(sa[a] * inva);
}

// ---------------------------------------------------------------------------
// 4b) pooling partials: grid (128 b, 2 halves), 256 thr, 200 f each
// ---------------------------------------------------------------------------
__global__ __launch_bounds__(256) void pool_kernel()
{
    __shared__ float wq[LQv], wa[LAv];
    __shared__ float rd[256], rx[256], ry[256];

    const int b = blockIdx.x;
    const int f0 = blockIdx.y * 200;
    const int tid = threadIdx.x;

    for (int q = tid; q < LQv; q += 256) wq[q] = __uint_as_float(g_mq[b * LQv + q]);
    for (int a = tid; a < LAv; a += 256) wa[a] = __uint_as_float(g_ma[b * LAv + a]);
    __syncthreads();

    float d = 0.0f, x = 0.0f, y = 0.0f;
    if (tid < 200) {
        int f = f0 + tid;
        const float* qp = g_Q + (size_t)b * LQv * FILT + f;
        float accq = 0.0f;
#pragma unroll 8
        for (int q = 0; q < LQv; q++) accq += qp[(size_t)q * FILT] * wq[q];
        const float* ap = g_A + (size_t)b * LAv * FILT + f;
        float acca = 0.0f;
#pragma unroll 8
        for (int a = 0; a < LAv; a++) acca += ap[(size_t)a * FILT] * wa[a];
        d = accq * acca; x = accq * accq; y = acca * acca;
    }
    rd[tid] = d; rx[tid] = x; ry[tid] = y;
    __syncthreads();
#pragma unroll
    for (int s = 128; s > 0; s >>= 1) {
        if (tid < s) {
            rd[tid] += rd[tid + s];
            rx[tid] += rx[tid + s];
            ry[tid] += ry[tid + s];
        }
        __syncthreads();
    }
    if (tid == 0) {
        atomicAdd(&g_dxy[b * 4 + 0], rd[0]);
        atomicAdd(&g_dxy[b * 4 + 1], rx[0]);
        atomicAdd(&g_dxy[b * 4 + 2], ry[0]);
    }
}

// ---------------------------------------------------------------------------
// 4c) final cosine
// ---------------------------------------------------------------------------
__global__ __launch_bounds__(128) void final_out_kernel(float* __restrict__ out)
{
    int b = threadIdx.x;
    float D = g_dxy[b * 4 + 0];
    float X = g_dxy[b * 4 + 1];
    float Y = g_dxy[b * 4 + 2];
    float nq = fmaxf(sqrtf(X), 1e-8f);
    float na = fmaxf(sqrtf(Y), 1e-8f);
    out[b] = D / (nq * na);
}

// ---------------------------------------------------------------------------
// launch — two streams: convA on s2 overlaps convQ + gemm_T on main
// ---------------------------------------------------------------------------
extern "C" void kernel_launch(void* const* d_in, const int* in_sizes, int n_in,
                              void* d_out, int out_size)
{
    const int*   questions = (const int*)d_in[0];
    const int*   answers   = (const int*)d_in[1];
    const float* emb       = (const float*)d_in[2];
    const float* conv_w    = (const float*)d_in[3];
    const float* conv_b    = (const float*)d_in[4];
    const float* W         = (const float*)d_in[5];
    float*       out       = (float*)d_out;

    (void)in_sizes; (void)n_in; (void)out_size;

    static bool init_done = false;
    static cudaStream_t s2;
    static cudaEvent_t evFork, evJoin;
    if (!init_done) {
        cudaFuncSetAttribute(conv_encode_kernel,
                             cudaFuncAttributeMaxDynamicSharedMemorySize, SMEM_CONV);
        cudaFuncSetAttribute(gemm_T_kernel,
                             cudaFuncAttributeMaxDynamicSharedMemorySize, SMEM_T);
        cudaFuncSetAttribute(gemm_G_kernel,
                             cudaFuncAttributeMaxDynamicSharedMemorySize, SMEM_G);
        cudaStreamCreateWithFlags(&s2, cudaStreamNonBlocking);
        cudaEventCreateWithFlags(&evFork, cudaEventDisableTiming);
        cudaEventCreateWithFlags(&evJoin, cudaEventDisableTiming);
        init_done = true;
    }

    init_max_kernel<<<(BATCH * LAv + 255) / 256, 256>>>();
    transpose_w_kernel<<<(KCONV * FILT + 255) / 256, 256>>>(conv_w);

    // fork: convA on s2 after transpose
    cudaEventRecord(evFork, 0);
    cudaStreamWaitEvent(s2, evFork, 0);

    conv_encode_kernel<<<dim3(4, FILT / 80, BATCH), 128, SMEM_CONV, s2>>>(
        questions, answers, emb, conv_b, 0);   // answers

    // main stream: convQ then T (Q-only dependency)
    conv_encode_kernel<<<dim3(1, FILT / 80, BATCH), 128, SMEM_CONV>>>(
        questions, answers, emb, conv_b, 1);   // questions
    gemm_T_kernel<<<dim3(FILT / 80, 1, BATCH), 128, SMEM_T>>>(W);

    // join: G needs A (s2) and T (main)
    cudaEventRecord(evJoin, s2);
    cudaStreamWaitEvent(0, evJoin, 0);

    gemm_G_kernel<<<dim3(LAv / 128, BATCH), 256, SMEM_G>>>();

    softmax_kernel<<<BATCH, 256>>>();
    pool_kernel<<<dim3(BATCH, 2), 256>>>();
    final_out_kernel<<<1, 128>>>(out);
}

// round 9
// speedup vs baseline: 1.2589x; 1.0558x over previous
#include <cuda_runtime.h>
#include <math.h>

#define BATCH 128
#define LQv   128
#define LAv   512
#define EMBD  300
#define FILT  400
#define EPAD  320
#define KCONV (3 * EPAD)   // 960

// ---- scratch (static __device__: no allocations allowed) ----
__device__ float    g_Q[BATCH * LQv * FILT];
__device__ float    g_A[BATCH * LAv * FILT];
__device__ float    g_T[BATCH * LQv * FILT];
__device__ unsigned g_Bw[KCONV * FILT];   // packed: [ntile=5][k'=960][80] tf32 bits
__device__ unsigned g_mq[BATCH * LQv];
__device__ unsigned g_ma[BATCH * LAv];
__device__ float    g_dxy[BATCH * 4];

__device__ __forceinline__ unsigned enc_f(float f) {
    int i = __float_as_int(f);
    return (unsigned)(i ^ ((i >> 31) | 0x80000000));
}
__device__ __forceinline__ float dec_f(unsigned u) {
    int i = (u & 0x80000000u) ? (int)(u ^ 0x80000000u) : ~(int)u;
    return __int_as_float(i);
}
__device__ __forceinline__ unsigned f2tf(float f) {
    unsigned u;
    asm("cvt.rna.tf32.f32 %0, %1;" : "=r"(u) : "f"(f));
    return u;
}
__device__ __forceinline__ void mma8(float* c, const unsigned* a, const unsigned* b) {
    asm("mma.sync.aligned.m16n8k8.row.col.f32.tf32.tf32.f32 "
        "{%0,%1,%2,%3},{%4,%5,%6,%7},{%8,%9},{%0,%1,%2,%3};"
        : "+f"(c[0]), "+f"(c[1]), "+f"(c[2]), "+f"(c[3])
        : "r"(a[0]), "r"(a[1]), "r"(a[2]), "r"(a[3]), "r"(b[0]), "r"(b[1]));
}
__device__ __forceinline__ void cp16(void* sptr, const void* gptr, int bytes) {
    unsigned s = (unsigned)__cvta_generic_to_shared(sptr);
    asm volatile("cp.async.cg.shared.global [%0], [%1], 16, %2;"
                 :: "r"(s), "l"(gptr), "r"(bytes));
}
__device__ __forceinline__ void cp16f(void* sptr, const void* gptr) {
    unsigned s = (unsigned)__cvta_generic_to_shared(sptr);
    asm volatile("cp.async.bulk.prefetch.L2.global [%0], 16;" :: "l"(gptr));
    // (dummy line removed below — see real cp16f)
}
#define CP_COMMIT() asm volatile("cp.async.commit_group;")
#define CP_WAIT1()  asm volatile("cp.async.wait_group 1;")

// real 16B cp.async (the above decl is replaced here to keep one definition)
__device__ __forceinline__ void cp16g(void* sptr, const void* gptr) {
    unsigned s = (unsigned)__cvta_generic_to_shared(sptr);
    asm volatile("cp.async.cg.shared.global [%0], [%1], 16;"
                 :: "r"(s), "l"(gptr));
}

// ---- mbarrier + bulk helpers ----
__device__ __forceinline__ void mbar_init(unsigned addr, unsigned count) {
    asm volatile("mbarrier.init.shared.b64 [%0], %1;" :: "r"(addr), "r"(count) : "memory");
}
__device__ __forceinline__ void mbar_expect_tx(unsigned addr, unsigned bytes) {
    asm volatile("mbarrier.arrive.expect_tx.shared.b64 _, [%0], %1;"
                 :: "r"(addr), "r"(bytes) : "memory");
}
__device__ __forceinline__ void mbar_wait(unsigned addr, unsigned phase) {
    unsigned done = 0;
    while (!done) {
        asm volatile(
            "{\n\t.reg .pred p;\n\t"
            "mbarrier.try_wait.parity.shared.b64 p, [%1], %2;\n\t"
            "selp.b32 %0, 1, 0, p;\n\t}"
            : "=r"(done) : "r"(addr), "r"(phase) : "memory");
    }
}
__device__ __forceinline__ void cp_bulk(void* sptr, const void* gptr,
                                        unsigned bytes, unsigned mbar) {
    unsigned s = (unsigned)__cvta_generic_to_shared(sptr);
    asm volatile(
        "cp.async.bulk.shared::cta.global.mbarrier::complete_tx::bytes "
        "[%0], [%1], %2, [%3];"
        :: "r"(s), "l"(gptr), "r"(bytes), "r"(mbar) : "memory");
}

// ---------------------------------------------------------------------------
// 0) init
// ---------------------------------------------------------------------------
__global__ void init_max_kernel() {
    int idx = blockIdx.x * blockDim.x + threadIdx.x;
    unsigned v = enc_f(-2.0f);
    if (idx < BATCH * LQv) g_mq[idx] = v;
    if (idx < BATCH * LAv) g_ma[idx] = v;
    if (idx < BATCH * 4)   g_dxy[idx] = 0.0f;
}

// pack conv weights: g_Bw[nt][kp][nn] = tf32(cw[nt*80+nn][e][koff]), kp = koff*EPAD+e
__global__ void transpose_w_kernel(const float* __restrict__ cw) {
    int idx = blockIdx.x * blockDim.x + threadIdx.x;
    if (idx >= 5 * KCONV * 80) return;
    int nt = idx / (KCONV * 80);
    int r  = idx - nt * (KCONV * 80);
    int kp = r / 80, nn = r - kp * 80;
    int n = nt * 80 + nn;
    int koff = kp / EPAD, e = kp - koff * EPAD;
    float v = (e < EMBD) ? cw[(size_t)n * (EMBD * 3) + e * 3 + koff] : 0.0f;
    g_Bw[idx] = f2tf(v);
}

// ---------------------------------------------------------------------------
// 1) conv encode: 128 thr, 4 warps (2m x 2n), warp 64x40, block 128 tok x 80 f.
//    E via cp.async (gather), B via cp.async.bulk + mbarrier (3 bulks/chunk).
// ---------------------------------------------------------------------------
#define C_KC 32
#define C_NCH (EPAD / C_KC)       // 10
#define E_PITCH 36
#define E_BUF  (130 * E_PITCH)    // 4680
#define B_PITCH 80
#define B_KOFF (C_KC * B_PITCH)   // 2560
#define B_BUF  (3 * B_KOFF)       // 7680
#define B_BYTES (B_KOFF * 4)      // 10240 per ko
#define SM_MBAR 130               // two u64 mbarriers at words 130,132
#define SM_E_OFF 136
#define SM_B_OFF (SM_E_OFF + 2 * E_BUF)          // 9496
#define SMEM_CONV ((SM_B_OFF + 2 * B_BUF) * 4)   // 99424 B

__global__ __launch_bounds__(128, 2) void conv_encode_kernel(
    const int* __restrict__ qtok, const int* __restrict__ atok,
    const float* __restrict__ emb, const float* __restrict__ cb, int is_q)
{
    extern __shared__ unsigned sm[];
    int*      s_tok = (int*)sm;
    unsigned* E     = sm + SM_E_OFF;
    unsigned* Bsm   = sm + SM_B_OFF;

    const int b   = blockIdx.z;
    const int nt  = blockIdx.y;
    const int n0  = nt * 80;
    const int tid = threadIdx.x;
    const int wid = tid >> 5, lane = tid & 31;
    const int g   = lane >> 2, tig = lane & 3;
    const int wm  = wid & 1,  wn  = wid >> 1;
    const int mwb = wm * 64,  nwb = wn * 40;

    unsigned smem_base;
    asm("{ .reg .u64 t; cvta.to.shared.u64 t, %1; cvt.u32.u64 %0, t; }"
        : "=r"(smem_base) : "l"((void*)sm));
    const unsigned mbar0 = smem_base + SM_MBAR * 4;        // byte addr, 8B aligned
    const unsigned mbar1 = smem_base + (SM_MBAR + 2) * 4;

    const int* tok = is_q ? qtok : atok;
    float* dst     = is_q ? g_Q : g_A;
    const int L    = is_q ? LQv : LAv;
    const int t0   = blockIdx.x * 128;

    if (tid == 0) { mbar_init(mbar0, 1); mbar_init(mbar1, 1); }
    for (int r = tid; r < 130; r += 128) {
        int tg = t0 + r - 1;
        s_tok[r] = (tg >= 0 && tg < L) ? tok[b * L + tg] : 0;
    }
    __syncthreads();

    auto prefetch = [&](int ch, int bs) {
        int ec = ch * C_KC;
        unsigned* Eb = E + bs * E_BUF;
        // E gather: 130 rows x 8 x 16B
        for (int i = tid; i < 130 * 8; i += 128) {
            int r = i >> 3, sg = i & 7;
            int e = ec + sg * 4;
            int el = 300 - e; el = el < 0 ? 0 : (el > 4 ? 4 : el);
            int bytes = el * 4;
            const float* src = emb + (bytes ? ((size_t)s_tok[r] * EMBD + e) : 0);
            cp16(&Eb[r * E_PITCH + sg * 4], src, bytes);
        }
        // B: 3 bulk copies (one per koff), contiguous 10240 B each
        if (tid == 0) {
            unsigned mb = bs ? mbar1 : mbar0;
            mbar_expect_tx(mb, 3 * B_BYTES);
            unsigned* Bb = Bsm + bs * B_BUF;
#pragma unroll
            for (int ko = 0; ko < 3; ko++) {
                const unsigned* src =
                    g_Bw + ((size_t)nt * KCONV + ko * EPAD + ec) * 80;
                cp_bulk(&Bb[ko * B_KOFF], src, B_BYTES, mb);
            }
        }
    };

    float c[4][5][4];
#pragma unroll
    for (int i = 0; i < 4; i++)
#pragma unroll
        for (int j = 0; j < 5; j++)
#pragma unroll
            for (int k = 0; k < 4; k++) c[i][j][k] = 0.0f;

    prefetch(0, 0);
    CP_COMMIT();

    for (int ch = 0; ch < C_NCH; ch++) {
        int bs = ch & 1;
        if (ch + 1 < C_NCH) prefetch(ch + 1, bs ^ 1);
        CP_COMMIT();
        CP_WAIT1();                                   // E of chunk ch landed
        mbar_wait(bs ? mbar1 : mbar0, (ch >> 1) & 1); // B of chunk ch landed
        __syncthreads();

        const unsigned* Eb = E + bs * E_BUF;
        const unsigned* Bb = Bsm + bs * B_BUF;

#pragma unroll
        for (int ko = 0; ko < 3; ko++) {
            const unsigned* Bk = Bb + ko * B_KOFF;
#pragma unroll
            for (int kb = 0; kb < C_KC / 8; kb++) {
                int kk = kb * 8;
                unsigned a[4][4];
#pragma unroll
                for (int ms = 0; ms < 4; ms++) {
                    int row = mwb + ms * 16 + g + ko;
                    a[ms][0] = Eb[(row)     * E_PITCH + kk + tig];
                    a[ms][1] = Eb[(row + 8) * E_PITCH + kk + tig];
                    a[ms][2] = Eb[(row)     * E_PITCH + kk + tig + 4];
                    a[ms][3] = Eb[(row + 8) * E_PITCH + kk + tig + 4];
                }
#pragma unroll
                for (int ns = 0; ns < 5; ns++) {
                    unsigned bf[2];
                    int nb = nwb + ns * 8 + g;
                    bf[0] = Bk[(kk + tig)     * B_PITCH + nb];
                    bf[1] = Bk[(kk + tig + 4) * B_PITCH + nb];
#pragma unroll
                    for (int ms = 0; ms < 4; ms++)
                        mma8(c[ms][ns], a[ms], bf);
                }
            }
        }
        __syncthreads();
    }

#pragma unroll
    for (int ms = 0; ms < 4; ms++) {
#pragma unroll
        for (int ns = 0; ns < 5; ns++) {
            int col = n0 + nwb + ns * 8 + 2 * tig;
            float2 bias = *(const float2*)&cb[col];
            int row0 = t0 + mwb + ms * 16 + g;
            *(float2*)&dst[((size_t)b * L + row0) * FILT + col] =
                make_float2(c[ms][ns][0] + bias.x, c[ms][ns][1] + bias.y);
            *(float2*)&dst[((size_t)b * L + row0 + 8) * FILT + col] =
                make_float2(c[ms][ns][2] + bias.x, c[ms][ns][3] + bias.y);
        }
    }
}

// ---------------------------------------------------------------------------
// 2) T = Qm @ W : 128 thr, warp 64x40, 2-stage cp.async (R5 config)
// ---------------------------------------------------------------------------
#define T_KC 40
#define T_AP 44
#define T_BP 88
#define T_ABUF (128 * T_AP)
#define T_BOFF (2 * T_ABUF)
#define T_BBUF (T_KC * T_BP)
#define SMEM_T ((T_BOFF + 2 * T_BBUF) * 4)

__global__ __launch_bounds__(128, 2) void gemm_T_kernel(const float* __restrict__ W)
{
    extern __shared__ unsigned sm[];
    unsigned* Asm = sm;
    unsigned* Bsm = sm + T_BOFF;

    const int b  = blockIdx.z;
    const int n0 = blockIdx.x * 80;
    const int tid  = threadIdx.x;
    const int wid  = tid >> 5, lane = tid & 31;
    const int g    = lane >> 2, tig = lane & 3;
    const int wm   = wid & 1,  wn  = wid >> 1;
    const int mwb  = wm * 64, nwb = wn * 40;

    const float* Qb = g_Q + (size_t)b * LQv * FILT;

    auto prefetch = [&](int ch, int bs) {
        int k0 = ch * T_KC;
        unsigned* Ab = Asm + bs * T_ABUF;
        unsigned* Bb = Bsm + bs * T_BBUF;
#pragma unroll
        for (int it = 0; it < 10; it++) {
            int i = tid + it * 128;
            int m = i / 10, k4 = i - m * 10;
            cp16g(&Ab[m * T_AP + k4 * 4], Qb + (size_t)m * FILT + k0 + k4 * 4);
        }
        for (int i = tid; i < T_KC * 20; i += 128) {
            int kc = i / 20, sg = i - kc * 20;
            cp16g(&Bb[kc * T_BP + sg * 4], W + (size_t)(k0 + kc) * FILT + n0 + sg * 4);
        }
    };

    float c[4][5][4];
#pragma unroll
    for (int i = 0; i < 4; i++)
#pragma unroll
        for (int j = 0; j < 5; j++)
#pragma unroll
            for (int k = 0; k < 4; k++) c[i][j][k] = 0.0f;

    prefetch(0, 0);
    CP_COMMIT();

    for (int ch = 0; ch < FILT / T_KC; ch++) {
        int bs = ch & 1;
        if (ch + 1 < FILT / T_KC) prefetch(ch + 1, bs ^ 1);
        CP_COMMIT();
        CP_WAIT1();
        __syncthreads();

        const unsigned* Ab = Asm + bs * T_ABUF;
        const unsigned* Bb = Bsm + bs * T_BBUF;

#pragma unroll
        for (int kb = 0; kb < T_KC / 8; kb++) {
            int kk = kb * 8;
            unsigned a[4][4];
#pragma unroll
            for (int ms = 0; ms < 4; ms++) {
                int row = mwb + ms * 16 + g;
                a[ms][0] = Ab[(row)     * T_AP + kk + tig];
                a[ms][1] = Ab[(row + 8) * T_AP + kk + tig];
                a[ms][2] = Ab[(row)     * T_AP + kk + tig + 4];
                a[ms][3] = Ab[(row + 8) * T_AP + kk + tig + 4];
            }
#pragma unroll
            for (int ns = 0; ns < 5; ns++) {
                unsigned bf[2];
                int nb = nwb + ns * 8 + g;
                bf[0] = Bb[(kk + tig)     * T_BP + nb];
                bf[1] = Bb[(kk + tig + 4) * T_BP + nb];
#pragma unroll
                for (int ms = 0; ms < 4; ms++)
                    mma8(c[ms][ns], a[ms], bf);
            }
        }
        __syncthreads();
    }

#pragma unroll
    for (int ms = 0; ms < 4; ms++) {
#pragma unroll
        for (int ns = 0; ns < 5; ns++) {
            int col = n0 + nwb + ns * 8 + 2 * tig;
            int row0 = mwb + ms * 16 + g;
            *(float2*)&g_T[((size_t)b * LQv + row0) * FILT + col] =
                make_float2(c[ms][ns][0], c[ms][ns][1]);
            *(float2*)&g_T[((size_t)b * LQv + row0 + 8) * FILT + col] =
                make_float2(c[ms][ns][2], c[ms][ns][3]);
        }
    }
}

// ---------------------------------------------------------------------------
// 3) G = tanh(T @ A^T) fused maxes: 256 thr, 8 warps (2m x 4n), warp 64x32,
//    block 128 x 128, 2-stage (R5 config)
// ---------------------------------------------------------------------------
#define G_KC 40
#define G_AP 44
#define G_ABUF (128 * G_AP)
#define G_BOFF (2 * G_ABUF)
#define G_BBUF (128 * G_AP)
#define G_RED  (G_BOFF + 2 * G_BBUF)
#define SMEM_G ((G_RED + 256) * 4)

__global__ __launch_bounds__(256, 2) void gemm_G_kernel()
{
    extern __shared__ unsigned sm[];
    unsigned* Asm  = sm;
    unsigned* Bsm  = sm + G_BOFF;
    unsigned* srow = sm + G_RED;
    unsigned* scol = sm + G_RED + 128;

    const int b  = blockIdx.y;
    const int a0 = blockIdx.x * 128;
    const int tid  = threadIdx.x;
    const int wid  = tid >> 5, lane = tid & 31;
    const int g    = lane >> 2, tig = lane & 3;
    const int wm   = wid & 1,  wn  = wid >> 1;
    const int mwb  = wm * 64, nwb = wn * 32;

    if (tid < 128) { srow[tid] = enc_f(-2.0f); scol[tid] = enc_f(-2.0f); }

    const float* Tb  = g_T + (size_t)b * LQv * FILT;
    const float* Ab0 = g_A + ((size_t)b * LAv + a0) * FILT;

    auto prefetch = [&](int ch, int bs) {
        int k0 = ch * G_KC;
        unsigned* Abuf = Asm + bs * G_ABUF;
        unsigned* Bbuf = Bsm + bs * G_BBUF;
#pragma unroll
        for (int it = 0; it < 5; it++) {
            int i = tid + it * 256;
            int m = i / 10, k4 = i - m * 10;
            cp16g(&Abuf[m * G_AP + k4 * 4], Tb + (size_t)m * FILT + k0 + k4 * 4);
        }
#pragma unroll
        for (int it = 0; it < 5; it++) {
            int i = tid + it * 256;
            int n = i / 10, k4 = i - n * 10;
            cp16g(&Bbuf[n * G_AP + k4 * 4], Ab0 + (size_t)n * FILT + k0 + k4 * 4);
        }
    };

    float c[4][4][4];
#pragma unroll
    for (int i = 0; i < 4; i++)
#pragma unroll
        for (int j = 0; j < 4; j++)
#pragma unroll
            for (int k = 0; k < 4; k++) c[i][j][k] = 0.0f;

    prefetch(0, 0);
    CP_COMMIT();

    for (int ch = 0; ch < FILT / G_KC; ch++) {
        int bs = ch & 1;
        if (ch + 1 < FILT / G_KC) prefetch(ch + 1, bs ^ 1);
        CP_COMMIT();
        CP_WAIT1();
        __syncthreads();

        const unsigned* Abuf = Asm + bs * G_ABUF;
        const unsigned* Bbuf = Bsm + bs * G_BBUF;

#pragma unroll
        for (int kb = 0; kb < G_KC / 8; kb++) {
            int kk = kb * 8;
            unsigned a[4][4];
#pragma unroll
            for (int ms = 0; ms < 4; ms++) {
                int row = mwb + ms * 16 + g;
                a[ms][0] = Abuf[(row)     * G_AP + kk + tig];
                a[ms][1] = Abuf[(row + 8) * G_AP + kk + tig];
                a[ms][2] = Abuf[(row)     * G_AP + kk + tig + 4];
                a[ms][3] = Abuf[(row + 8) * G_AP + kk + tig + 4];
            }
#pragma unroll
            for (int ns = 0; ns < 4; ns++) {
                unsigned bf[2];
                int nb = nwb + ns * 8 + g;
                bf[0] = Bbuf[nb * G_AP + kk + tig];
                bf[1] = Bbuf[nb * G_AP + kk + tig + 4];
#pragma unroll
                for (int ms = 0; ms < 4; ms++)
                    mma8(c[ms][ns], a[ms], bf);
            }
        }
        __syncthreads();
    }

#pragma unroll
    for (int ms = 0; ms < 4; ms++) {
        float r0 = -2.0f, r1 = -2.0f;
#pragma unroll
        for (int ns = 0; ns < 4; ns++) {
#pragma unroll
            for (int k = 0; k < 4; k++) c[ms][ns][k] = tanhf(c[ms][ns][k]);
            r0 = fmaxf(r0, fmaxf(c[ms][ns][0], c[ms][ns][1]));
            r1 = fmaxf(r1, fmaxf(c[ms][ns][2], c[ms][ns][3]));
        }
        atomicMax(&srow[mwb + ms * 16 + g],     enc_f(r0));
        atomicMax(&srow[mwb + ms * 16 + g + 8], enc_f(r1));
    }
#pragma unroll
    for (int ns = 0; ns < 4; ns++) {
        float c0 = -2.0f, c1 = -2.0f;
#pragma unroll
        for (int ms = 0; ms < 4; ms++) {
            c0 = fmaxf(c0, fmaxf(c[ms][ns][0], c[ms][ns][2]));
            c1 = fmaxf(c1, fmaxf(c[ms][ns][1], c[ms][ns][3]));
        }
        int nb = nwb + ns * 8 + 2 * tig;
        atomicMax(&scol[nb],     enc_f(c0));
        atomicMax(&scol[nb + 1], enc_f(c1));
    }
    __syncthreads();

    if (tid < 128) {
        atomicMax(&g_mq[b * LQv + tid], srow[tid]);
        atomicMax(&g_ma[b * LAv + a0 + tid], scol[tid]);
    }
}

// ---------------------------------------------------------------------------
// 4a) per-batch softmax; writes normalized weights back into g_mq / g_ma
// ---------------------------------------------------------------------------
__device__ __forceinline__ float warp_max(float v) {
#pragma unroll
    for (int o = 16; o > 0; o >>= 1) v = fmaxf(v, __shfl_xor_sync(0xffffffffu, v, o));
    return v;
}
__device__ __forceinline__ float warp_sum(float v) {
#pragma unroll
    for (int o = 16; o > 0; o >>= 1) v += __shfl_xor_sync(0xffffffffu, v, o);
    return v;
}

__global__ __launch_bounds__(256) void softmax_kernel()
{
    __shared__ float sq[LQv], sa[LAv];
    __shared__ float smax[2], ssum[2];

    const int b = blockIdx.x;
    const int tid = threadIdx.x;
    const int lane = tid & 31;

    for (int q = tid; q < LQv; q += 256) sq[q] = dec_f(g_mq[b * LQv + q]);
    for (int a = tid; a < LAv; a += 256) sa[a] = dec_f(g_ma[b * LAv + a]);
    __syncthreads();

    if (tid < 32) {
        float m = -1e30f;
        for (int q = lane; q < LQv; q += 32) m = fmaxf(m, sq[q]);
        m = warp_max(m);
        if (lane == 0) smax[0] = m;
    } else if (tid < 64) {
        float m = -1e30f;
        for (int a = lane; a < LAv; a += 32) m = fmaxf(m, sa[a]);
        m = warp_max(m);
        if (lane == 0) smax[1] = m;
    }
    __syncthreads();
    for (int q = tid; q < LQv; q += 256) sq[q] = expf(sq[q] - smax[0]);
    for (int a = tid; a < LAv; a += 256) sa[a] = expf(sa[a] - smax[1]);
    __syncthreads();
    if (tid < 32) {
        float s = 0.0f;
        for (int q = lane; q < LQv; q += 32) s += sq[q];
        s = warp_sum(s);
        if (lane == 0) ssum[0] = s;
    } else if (tid < 64) {
        float s = 0.0f;
        for (int a = lane; a < LAv; a += 32) s += sa[a];
        s = warp_sum(s);
        if (lane == 0) ssum[1] = s;
    }
    __syncthreads();
    float invq = 1.0f / ssum[0], inva = 1.0f / ssum[1];
    for (int q = tid; q < LQv; q += 256)
        g_mq[b * LQv + q] = __float_as_uint(sq[q] * invq);
    for (int a = tid; a < LAv; a += 256)
        g_ma[b * LAv + a] = __float_as_uint(sa[a] * inva);
}

// ---------------------------------------------------------------------------
// 4b) pooling partials: grid (128 b, 2 halves), 256 thr, 200 f each
// ---------------------------------------------------------------------------
__global__ __launch_bounds__(256) void pool_kernel()
{
    __shared__ float wq[LQv], wa[LAv];
    __shared__ float rd[256], rx[256], ry[256];

    const int b = blockIdx.x;
    const int f0 = blockIdx.y * 200;
    const int tid = threadIdx.x;

    for (int q = tid; q < LQv; q += 256) wq[q] = __uint_as_float(g_mq[b * LQv + q]);
    for (int a = tid; a < LAv; a += 256) wa[a] = __uint_as_float(g_ma[b * LAv + a]);
    __syncthreads();

    float d = 0.0f, x = 0.0f, y = 0.0f;
    if (tid < 200) {
        int f = f0 + tid;
        const float* qp = g_Q + (size_t)b * LQv * FILT + f;
        float accq = 0.0f;
#pragma unroll 8
        for (int q = 0; q < LQv; q++) accq += qp[(size_t)q * FILT] * wq[q];
        const float* ap = g_A + (size_t)b * LAv * FILT + f;
        float acca = 0.0f;
#pragma unroll 8
        for (int a = 0; a < LAv; a++) acca += ap[(size_t)a * FILT] * wa[a];
        d = accq * acca; x = accq * accq; y = acca * acca;
    }
    rd[tid] = d; rx[tid] = x; ry[tid] = y;
    __syncthreads();
#pragma unroll
    for (int s = 128; s > 0; s >>= 1) {
        if (tid < s) {
            rd[tid] += rd[tid + s];
            rx[tid] += rx[tid + s];
            ry[tid] += ry[tid + s];
        }
        __syncthreads();
    }
    if (tid == 0) {
        atomicAdd(&g_dxy[b * 4 + 0], rd[0]);
        atomicAdd(&g_dxy[b * 4 + 1], rx[0]);
        atomicAdd(&g_dxy[b * 4 + 2], ry[0]);
    }
}

// ---------------------------------------------------------------------------
// 4c) final cosine
// ---------------------------------------------------------------------------
__global__ __launch_bounds__(128) void final_out_kernel(float* __restrict__ out)
{
    int b = threadIdx.x;
    float D = g_dxy[b * 4 + 0];
    float X = g_dxy[b * 4 + 1];
    float Y = g_dxy[b * 4 + 2];
    float nq = fmaxf(sqrtf(X), 1e-8f);
    float na = fmaxf(sqrtf(Y), 1e-8f);
    out[b] = D / (nq * na);
}

// ---------------------------------------------------------------------------
// launch — two streams: convA on s2 overlaps convQ + gemm_T on main
// ---------------------------------------------------------------------------
extern "C" void kernel_launch(void* const* d_in, const int* in_sizes, int n_in,
                              void* d_out, int out_size)
{
    const int*   questions = (const int*)d_in[0];
    const int*   answers   = (const int*)d_in[1];
    const float* emb       = (const float*)d_in[2];
    const float* conv_w    = (const float*)d_in[3];
    const float* conv_b    = (const float*)d_in[4];
    const float* W         = (const float*)d_in[5];
    float*       out       = (float*)d_out;

    (void)in_sizes; (void)n_in; (void)out_size;

    static bool init_done = false;
    static cudaStream_t s2;
    static cudaEvent_t evFork, evJoin;
    if (!init_done) {
        cudaFuncSetAttribute(conv_encode_kernel,
                             cudaFuncAttributeMaxDynamicSharedMemorySize, SMEM_CONV);
        cudaFuncSetAttribute(gemm_T_kernel,
                             cudaFuncAttributeMaxDynamicSharedMemorySize, SMEM_T);
        cudaFuncSetAttribute(gemm_G_kernel,
                             cudaFuncAttributeMaxDynamicSharedMemorySize, SMEM_G);
        cudaStreamCreateWithFlags(&s2, cudaStreamNonBlocking);
        cudaEventCreateWithFlags(&evFork, cudaEventDisableTiming);
        cudaEventCreateWithFlags(&evJoin, cudaEventDisableTiming);
        init_done = true;
    }

    init_max_kernel<<<(BATCH * LAv + 255) / 256, 256>>>();
    transpose_w_kernel<<<(5 * KCONV * 80 + 255) / 256, 256>>>(conv_w);

    // fork: convA on s2 after transpose
    cudaEventRecord(evFork, 0);
    cudaStreamWaitEvent(s2, evFork, 0);

    conv_encode_kernel<<<dim3(4, 5, BATCH), 128, SMEM_CONV, s2>>>(
        questions, answers, emb, conv_b, 0);   // answers

    // main stream: convQ then T (Q-only dependency)
    conv_encode_kernel<<<dim3(1, 5, BATCH), 128, SMEM_CONV>>>(
        questions, answers, emb, conv_b, 1);   // questions
    gemm_T_kernel<<<dim3(FILT / 80, 1, BATCH), 128, SMEM_T>>>(W);

    // join: G needs A (s2) and T (main)
    cudaEventRecord(evJoin, s2);
    cudaStreamWaitEvent(0, evJoin, 0);

    gemm_G_kernel<<<dim3(LAv / 128, BATCH), 256, SMEM_G>>>();

    softmax_kernel<<<BATCH, 256>>>();
    pool_kernel<<<dim3(BATCH, 2), 256>>>();
    final_out_kernel<<<1, 128>>>(out);
}

// round 10
// speedup vs baseline: 1.2641x; 1.0041x over previous
#include <cuda_runtime.h>
#include <math.h>

#define BATCH 128
#define LQv   128
#define LAv   512
#define EMBD  300
#define FILT  400
#define EPAD  320
#define KCONV (3 * EPAD)   // 960

// ---- scratch (static __device__: no allocations allowed) ----
__device__ float    g_Q[BATCH * LQv * FILT];
__device__ float    g_A[BATCH * LAv * FILT];
__device__ float    g_T[BATCH * LQv * FILT];
__device__ unsigned g_Bw[KCONV * FILT];   // packed: [ntile=5][k'=960][80] tf32 bits
__device__ unsigned g_mq[BATCH * LQv];
__device__ unsigned g_ma[BATCH * LAv];
__device__ float    g_dxy[BATCH * 4];

__device__ __forceinline__ unsigned enc_f(float f) {
    int i = __float_as_int(f);
    return (unsigned)(i ^ ((i >> 31) | 0x80000000));
}
__device__ __forceinline__ float dec_f(unsigned u) {
    int i = (u & 0x80000000u) ? (int)(u ^ 0x80000000u) : ~(int)u;
    return __int_as_float(i);
}
__device__ __forceinline__ unsigned f2tf(float f) {
    unsigned u;
    asm("cvt.rna.tf32.f32 %0, %1;" : "=r"(u) : "f"(f));
    return u;
}
__device__ __forceinline__ void mma8(float* c, const unsigned* a, const unsigned* b) {
    asm("mma.sync.aligned.m16n8k8.row.col.f32.tf32.tf32.f32 "
        "{%0,%1,%2,%3},{%4,%5,%6,%7},{%8,%9},{%0,%1,%2,%3};"
        : "+f"(c[0]), "+f"(c[1]), "+f"(c[2]), "+f"(c[3])
        : "r"(a[0]), "r"(a[1]), "r"(a[2]), "r"(a[3]), "r"(b[0]), "r"(b[1]));
}
__device__ __forceinline__ void cp16(void* sptr, const void* gptr, int bytes) {
    unsigned s = (unsigned)__cvta_generic_to_shared(sptr);
    asm volatile("cp.async.cg.shared.global [%0], [%1], 16, %2;"
                 :: "r"(s), "l"(gptr), "r"(bytes));
}
__device__ __forceinline__ void cp16g(void* sptr, const void* gptr) {
    unsigned s = (unsigned)__cvta_generic_to_shared(sptr);
    asm volatile("cp.async.cg.shared.global [%0], [%1], 16;"
                 :: "r"(s), "l"(gptr));
}
#define CP_COMMIT() asm volatile("cp.async.commit_group;")
#define CP_WAIT1()  asm volatile("cp.async.wait_group 1;")

// ---- mbarrier + bulk helpers ----
__device__ __forceinline__ void mbar_init(unsigned addr, unsigned count) {
    asm volatile("mbarrier.init.shared.b64 [%0], %1;" :: "r"(addr), "r"(count) : "memory");
}
__device__ __forceinline__ void mbar_expect_tx(unsigned addr, unsigned bytes) {
    asm volatile("mbarrier.arrive.expect_tx.shared.b64 _, [%0], %1;"
                 :: "r"(addr), "r"(bytes) : "memory");
}
__device__ __forceinline__ void mbar_wait(unsigned addr, unsigned phase) {
    unsigned done = 0;
    while (!done) {
        asm volatile(
            "{\n\t.reg .pred p;\n\t"
            "mbarrier.try_wait.parity.shared.b64 p, [%1], %2;\n\t"
            "selp.b32 %0, 1, 0, p;\n\t}"
            : "=r"(done) : "r"(addr), "r"(phase) : "memory");
    }
}
__device__ __forceinline__ void cp_bulk(void* sptr, const void* gptr,
                                        unsigned bytes, unsigned mbar) {
    unsigned s = (unsigned)__cvta_generic_to_shared(sptr);
    asm volatile(
        "cp.async.bulk.shared::cta.global.mbarrier::complete_tx::bytes "
        "[%0], [%1], %2, [%3];"
        :: "r"(s), "l"(gptr), "r"(bytes), "r"(mbar) : "memory");
}
__device__ __forceinline__ unsigned smem_u32(const void* p) {
    unsigned r;
    asm("{ .reg .u64 t; cvta.to.shared.u64 t, %1; cvt.u32.u64 %0, t; }"
        : "=r"(r) : "l"(p));
    return r;
}

// ---------------------------------------------------------------------------
// 0) init
// ---------------------------------------------------------------------------
__global__ void init_max_kernel() {
    int idx = blockIdx.x * blockDim.x + threadIdx.x;
    unsigned v = enc_f(-2.0f);
    if (idx < BATCH * LQv) g_mq[idx] = v;
    if (idx < BATCH * LAv) g_ma[idx] = v;
    if (idx < BATCH * 4)   g_dxy[idx] = 0.0f;
}

// pack conv weights: g_Bw[nt][kp][nn] = tf32(cw[nt*80+nn][e][koff]), kp = koff*EPAD+e
__global__ void transpose_w_kernel(const float* __restrict__ cw) {
    int idx = blockIdx.x * blockDim.x + threadIdx.x;
    if (idx >= 5 * KCONV * 80) return;
    int nt = idx / (KCONV * 80);
    int r  = idx - nt * (KCONV * 80);
    int kp = r / 80, nn = r - kp * 80;
    int n = nt * 80 + nn;
    int koff = kp / EPAD, e = kp - koff * EPAD;
    float v = (e < EMBD) ? cw[(size_t)n * (EMBD * 3) + e * 3 + koff] : 0.0f;
    g_Bw[idx] = f2tf(v);
}

// ---------------------------------------------------------------------------
// 1) conv encode: 128 thr, 4 warps (2m x 2n), warp 64x40, block 128 tok x 80 f.
//    E and B both via cp.async.bulk + mbarrier (tail E chunk via cp.async zfill).
// ---------------------------------------------------------------------------
#define C_KC 32
#define C_NCH (EPAD / C_KC)       // 10
#define E_PITCH 36
#define E_BUF  (130 * E_PITCH)    // 4680
#define B_PITCH 80
#define B_KOFF (C_KC * B_PITCH)   // 2560
#define B_BUF  (3 * B_KOFF)       // 7680
#define B_BYTES (B_KOFF * 4)      // 10240 per ko
#define E_BYTES (C_KC * 4)        // 128 per row
#define SM_MBAR 130
#define SM_E_OFF 136
#define SM_B_OFF (SM_E_OFF + 2 * E_BUF)
#define SMEM_CONV ((SM_B_OFF + 2 * B_BUF) * 4)   // 99424 B

__global__ __launch_bounds__(128, 2) void conv_encode_kernel(
    const int* __restrict__ qtok, const int* __restrict__ atok,
    const float* __restrict__ emb, const float* __restrict__ cb, int is_q)
{
    extern __shared__ unsigned sm[];
    int*      s_tok = (int*)sm;
    unsigned* E     = sm + SM_E_OFF;
    unsigned* Bsm   = sm + SM_B_OFF;

    const int b   = blockIdx.z;
    const int nt  = blockIdx.y;
    const int n0  = nt * 80;
    const int tid = threadIdx.x;
    const int wid = tid >> 5, lane = tid & 31;
    const int g   = lane >> 2, tig = lane & 3;
    const int wm  = wid & 1,  wn  = wid >> 1;
    const int mwb = wm * 64,  nwb = wn * 40;

    const unsigned smem_base = smem_u32(sm);
    const unsigned mbar0 = smem_base + SM_MBAR * 4;
    const unsigned mbar1 = smem_base + (SM_MBAR + 2) * 4;

    const int* tok = is_q ? qtok : atok;
    float* dst     = is_q ? g_Q : g_A;
    const int L    = is_q ? LQv : LAv;
    const int t0   = blockIdx.x * 128;

    if (tid == 0) { mbar_init(mbar0, 1); mbar_init(mbar1, 1); }
    for (int r = tid; r < 130; r += 128) {
        int tg = t0 + r - 1;
        s_tok[r] = (tg >= 0 && tg < L) ? tok[b * L + tg] : 0;
    }
    __syncthreads();

    auto prefetch = [&](int ch, int bs) {
        int ec = ch * C_KC;
        unsigned mb = bs ? mbar1 : mbar0;
        unsigned* Eb = E + bs * E_BUF;
        unsigned* Bb = Bsm + bs * B_BUF;
        bool fullE = (ec + C_KC <= EMBD);

        if (tid == 0) {
            unsigned bytes = 3 * B_BYTES + (fullE ? 130 * E_BYTES : 0);
            mbar_expect_tx(mb, bytes);
#pragma unroll
            for (int ko = 0; ko < 3; ko++) {
                const unsigned* src =
                    g_Bw + ((size_t)nt * KCONV + ko * EPAD + ec) * 80;
                cp_bulk(&Bb[ko * B_KOFF], src, B_BYTES, mb);
            }
        }
        if (fullE) {
            // one 128-B bulk per row, issued across all threads
            for (int r = tid; r < 130; r += 128)
                cp_bulk(&Eb[r * E_PITCH],
                        emb + (size_t)s_tok[r] * EMBD + ec, E_BYTES, mb);
        } else {
            // tail chunk: zfill cp.async (tracked by cp.async group)
            for (int i = tid; i < 130 * 8; i += 128) {
                int r = i >> 3, sg = i & 7;
                int e = ec + sg * 4;
                int el = 300 - e; el = el < 0 ? 0 : (el > 4 ? 4 : el);
                int bytes = el * 4;
                const float* src = emb + (bytes ? ((size_t)s_tok[r] * EMBD + e) : 0);
                cp16(&Eb[r * E_PITCH + sg * 4], src, bytes);
            }
        }
    };

    float c[4][5][4];
#pragma unroll
    for (int i = 0; i < 4; i++)
#pragma unroll
        for (int j = 0; j < 5; j++)
#pragma unroll
            for (int k = 0; k < 4; k++) c[i][j][k] = 0.0f;

    prefetch(0, 0);
    CP_COMMIT();

    for (int ch = 0; ch < C_NCH; ch++) {
        int bs = ch & 1;
        if (ch + 1 < C_NCH) prefetch(ch + 1, bs ^ 1);
        CP_COMMIT();
        CP_WAIT1();                                   // tail-chunk E (if any)
        mbar_wait(bs ? mbar1 : mbar0, (ch >> 1) & 1); // bulk E+B landed
        __syncthreads();

        const unsigned* Eb = E + bs * E_BUF;
        const unsigned* Bb = Bsm + bs * B_BUF;

#pragma unroll
        for (int ko = 0; ko < 3; ko++) {
            const unsigned* Bk = Bb + ko * B_KOFF;
#pragma unroll
            for (int kb = 0; kb < C_KC / 8; kb++) {
                int kk = kb * 8;
                unsigned a[4][4];
#pragma unroll
                for (int ms = 0; ms < 4; ms++) {
                    int row = mwb + ms * 16 + g + ko;
                    a[ms][0] = Eb[(row)     * E_PITCH + kk + tig];
                    a[ms][1] = Eb[(row + 8) * E_PITCH + kk + tig];
                    a[ms][2] = Eb[(row)     * E_PITCH + kk + tig + 4];
                    a[ms][3] = Eb[(row + 8) * E_PITCH + kk + tig + 4];
                }
#pragma unroll
                for (int ns = 0; ns < 5; ns++) {
                    unsigned bf[2];
                    int nb = nwb + ns * 8 + g;
                    bf[0] = Bk[(kk + tig)     * B_PITCH + nb];
                    bf[1] = Bk[(kk + tig + 4) * B_PITCH + nb];
#pragma unroll
                    for (int ms = 0; ms < 4; ms++)
                        mma8(c[ms][ns], a[ms], bf);
                }
            }
        }
        __syncthreads();
    }

#pragma unroll
    for (int ms = 0; ms < 4; ms++) {
#pragma unroll
        for (int ns = 0; ns < 5; ns++) {
            int col = n0 + nwb + ns * 8 + 2 * tig;
            float2 bias = *(const float2*)&cb[col];
            int row0 = t0 + mwb + ms * 16 + g;
            *(float2*)&dst[((size_t)b * L + row0) * FILT + col] =
                make_float2(c[ms][ns][0] + bias.x, c[ms][ns][1] + bias.y);
            *(float2*)&dst[((size_t)b * L + row0 + 8) * FILT + col] =
                make_float2(c[ms][ns][2] + bias.x, c[ms][ns][3] + bias.y);
        }
    }
}

// ---------------------------------------------------------------------------
// 2) T = Qm @ W : 128 thr, warp 64x40, 2-stage cp.async (hidden under convA)
// ---------------------------------------------------------------------------
#define T_KC 40
#define T_AP 44
#define T_BP 88
#define T_ABUF (128 * T_AP)
#define T_BOFF (2 * T_ABUF)
#define T_BBUF (T_KC * T_BP)
#define SMEM_T ((T_BOFF + 2 * T_BBUF) * 4)

__global__ __launch_bounds__(128, 2) void gemm_T_kernel(const float* __restrict__ W)
{
    extern __shared__ unsigned sm[];
    unsigned* Asm = sm;
    unsigned* Bsm = sm + T_BOFF;

    const int b  = blockIdx.z;
    const int n0 = blockIdx.x * 80;
    const int tid  = threadIdx.x;
    const int wid  = tid >> 5, lane = tid & 31;
    const int g    = lane >> 2, tig = lane & 3;
    const int wm   = wid & 1,  wn  = wid >> 1;
    const int mwb  = wm * 64, nwb = wn * 40;

    const float* Qb = g_Q + (size_t)b * LQv * FILT;

    auto prefetch = [&](int ch, int bs) {
        int k0 = ch * T_KC;
        unsigned* Ab = Asm + bs * T_ABUF;
        unsigned* Bb = Bsm + bs * T_BBUF;
#pragma unroll
        for (int it = 0; it < 10; it++) {
            int i = tid + it * 128;
            int m = i / 10, k4 = i - m * 10;
            cp16g(&Ab[m * T_AP + k4 * 4], Qb + (size_t)m * FILT + k0 + k4 * 4);
        }
        for (int i = tid; i < T_KC * 20; i += 128) {
            int kc = i / 20, sg = i - kc * 20;
            cp16g(&Bb[kc * T_BP + sg * 4], W + (size_t)(k0 + kc) * FILT + n0 + sg * 4);
        }
    };

    float c[4][5][4];
#pragma unroll
    for (int i = 0; i < 4; i++)
#pragma unroll
        for (int j = 0; j < 5; j++)
#pragma unroll
            for (int k = 0; k < 4; k++) c[i][j][k] = 0.0f;

    prefetch(0, 0);
    CP_COMMIT();

    for (int ch = 0; ch < FILT / T_KC; ch++) {
        int bs = ch & 1;
        if (ch + 1 < FILT / T_KC) prefetch(ch + 1, bs ^ 1);
        CP_COMMIT();
        CP_WAIT1();
        __syncthreads();

        const unsigned* Ab = Asm + bs * T_ABUF;
        const unsigned* Bb = Bsm + bs * T_BBUF;

#pragma unroll
        for (int kb = 0; kb < T_KC / 8; kb++) {
            int kk = kb * 8;
            unsigned a[4][4];
#pragma unroll
            for (int ms = 0; ms < 4; ms++) {
                int row = mwb + ms * 16 + g;
                a[ms][0] = Ab[(row)     * T_AP + kk + tig];
                a[ms][1] = Ab[(row + 8) * T_AP + kk + tig];
                a[ms][2] = Ab[(row)     * T_AP + kk + tig + 4];
                a[ms][3] = Ab[(row + 8) * T_AP + kk + tig + 4];
            }
#pragma unroll
            for (int ns = 0; ns < 5; ns++) {
                unsigned bf[2];
                int nb = nwb + ns * 8 + g;
                bf[0] = Bb[(kk + tig)     * T_BP + nb];
                bf[1] = Bb[(kk + tig + 4) * T_BP + nb];
#pragma unroll
                for (int ms = 0; ms < 4; ms++)
                    mma8(c[ms][ns], a[ms], bf);
            }
        }
        __syncthreads();
    }

#pragma unroll
    for (int ms = 0; ms < 4; ms++) {
#pragma unroll
        for (int ns = 0; ns < 5; ns++) {
            int col = n0 + nwb + ns * 8 + 2 * tig;
            int row0 = mwb + ms * 16 + g;
            *(float2*)&g_T[((size_t)b * LQv + row0) * FILT + col] =
                make_float2(c[ms][ns][0], c[ms][ns][1]);
            *(float2*)&g_T[((size_t)b * LQv + row0 + 8) * FILT + col] =
                make_float2(c[ms][ns][2], c[ms][ns][3]);
        }
    }
}

// ---------------------------------------------------------------------------
// 3) G = tanh(T @ A^T) fused maxes: 256 thr, 8 warps (2m x 4n), warp 64x32,
//    block 128 x 128, 2-stage cp.async.bulk + mbarrier (1 bulk per thread/chunk)
// ---------------------------------------------------------------------------
#define G_KC 40
#define G_AP 44
#define G_ABUF (128 * G_AP)
#define G_BOFF (2 * G_ABUF)
#define G_BBUF (128 * G_AP)
#define G_RED  (G_BOFF + 2 * G_BBUF)
#define G_MBAR (G_RED + 256)
#define SMEM_G ((G_MBAR + 8) * 4)
#define G_ROW_BYTES (G_KC * 4)    // 160

__global__ __launch_bounds__(256, 2) void gemm_G_kernel()
{
    extern __shared__ unsigned sm[];
    unsigned* Asm  = sm;
    unsigned* Bsm  = sm + G_BOFF;
    unsigned* srow = sm + G_RED;
    unsigned* scol = sm + G_RED + 128;

    const int b  = blockIdx.y;
    const int a0 = blockIdx.x * 128;
    const int tid  = threadIdx.x;
    const int wid  = tid >> 5, lane = tid & 31;
    const int g    = lane >> 2, tig = lane & 3;
    const int wm   = wid & 1,  wn  = wid >> 1;
    const int mwb  = wm * 64, nwb = wn * 32;

    const unsigned smem_base = smem_u32(sm);
    const unsigned mbar0 = smem_base + G_MBAR * 4;
    const unsigned mbar1 = smem_base + (G_MBAR + 2) * 4;

    if (tid == 0) { mbar_init(mbar0, 1); mbar_init(mbar1, 1); }
    if (tid < 128) { srow[tid] = enc_f(-2.0f); scol[tid] = enc_f(-2.0f); }
    __syncthreads();

    const float* Tb  = g_T + (size_t)b * LQv * FILT;
    const float* Ab0 = g_A + ((size_t)b * LAv + a0) * FILT;

    auto prefetch = [&](int ch, int bs) {
        int k0 = ch * G_KC;
        unsigned mb = bs ? mbar1 : mbar0;
        if (tid == 0) mbar_expect_tx(mb, 256 * G_ROW_BYTES);
        if (tid < 128) {
            cp_bulk(&(Asm + bs * G_ABUF)[tid * G_AP],
                    Tb + (size_t)tid * FILT + k0, G_ROW_BYTES, mb);
        } else {
            int n = tid - 128;
            cp_bulk(&(Bsm + bs * G_BBUF)[n * G_AP],
                    Ab0 + (size_t)n * FILT + k0, G_ROW_BYTES, mb);
        }
    };

    float c[4][4][4];
#pragma unroll
    for (int i = 0; i < 4; i++)
#pragma unroll
        for (int j = 0; j < 4; j++)
#pragma unroll
            for (int k = 0; k < 4; k++) c[i][j][k] = 0.0f;

    prefetch(0, 0);

    for (int ch = 0; ch < FILT / G_KC; ch++) {
        int bs = ch & 1;
        if (ch + 1 < FILT / G_KC) prefetch(ch + 1, bs ^ 1);
        mbar_wait(bs ? mbar1 : mbar0, (ch >> 1) & 1);
        __syncthreads();

        const unsigned* Abuf = Asm + bs * G_ABUF;
        const unsigned* Bbuf = Bsm + bs * G_BBUF;

#pragma unroll
        for (int kb = 0; kb < G_KC / 8; kb++) {
            int kk = kb * 8;
            unsigned a[4][4];
#pragma unroll
            for (int ms = 0; ms < 4; ms++) {
                int row = mwb + ms * 16 + g;
                a[ms][0] = Abuf[(row)     * G_AP + kk + tig];
                a[ms][1] = Abuf[(row + 8) * G_AP + kk + tig];
                a[ms][2] = Abuf[(row)     * G_AP + kk + tig + 4];
                a[ms][3] = Abuf[(row + 8) * G_AP + kk + tig + 4];
            }
#pragma unroll
            for (int ns = 0; ns < 4; ns++) {
                unsigned bf[2];
                int nb = nwb + ns * 8 + g;
                bf[0] = Bbuf[nb * G_AP + kk + tig];
                bf[1] = Bbuf[nb * G_AP + kk + tig + 4];
#pragma unroll
                for (int ms = 0; ms < 4; ms++)
                    mma8(c[ms][ns], a[ms], bf);
            }
        }
        __syncthreads();
    }

#pragma unroll
    for (int ms = 0; ms < 4; ms++) {
        float r0 = -2.0f, r1 = -2.0f;
#pragma unroll
        for (int ns = 0; ns < 4; ns++) {
#pragma unroll
            for (int k = 0; k < 4; k++) c[ms][ns][k] = tanhf(c[ms][ns][k]);
            r0 = fmaxf(r0, fmaxf(c[ms][ns][0], c[ms][ns][1]));
            r1 = fmaxf(r1, fmaxf(c[ms][ns][2], c[ms][ns][3]));
        }
        atomicMax(&srow[mwb + ms * 16 + g],     enc_f(r0));
        atomicMax(&srow[mwb + ms * 16 + g + 8], enc_f(r1));
    }
#pragma unroll
    for (int ns = 0; ns < 4; ns++) {
        float c0 = -2.0f, c1 = -2.0f;
#pragma unroll
        for (int ms = 0; ms < 4; ms++) {
            c0 = fmaxf(c0, fmaxf(c[ms][ns][0], c[ms][ns][2]));
            c1 = fmaxf(c1, fmaxf(c[ms][ns][1], c[ms][ns][3]));
        }
        int nb = nwb + ns * 8 + 2 * tig;
        atomicMax(&scol[nb],     enc_f(c0));
        atomicMax(&scol[nb + 1], enc_f(c1));
    }
    __syncthreads();

    if (tid < 128) {
        atomicMax(&g_mq[b * LQv + tid], srow[tid]);
        atomicMax(&g_ma[b * LAv + a0 + tid], scol[tid]);
    }
}

// ---------------------------------------------------------------------------
// 4a) per-batch softmax; writes normalized weights back into g_mq / g_ma
// ---------------------------------------------------------------------------
__device__ __forceinline__ float warp_max(float v) {
#pragma unroll
    for (int o = 16; o > 0; o >>= 1) v = fmaxf(v, __shfl_xor_sync(0xffffffffu, v, o));
    return v;
}
__device__ __forceinline__ float warp_sum(float v) {
#pragma unroll
    for (int o = 16; o > 0; o >>= 1) v += __shfl_xor_sync(0xffffffffu, v, o);
    return v;
}

__global__ __launch_bounds__(256) void softmax_kernel()
{
    __shared__ float sq[LQv], sa[LAv];
    __shared__ float smax[2], ssum[2];

    const int b = blockIdx.x;
    const int tid = threadIdx.x;
    const int lane = tid & 31;

    for (int q = tid; q < LQv; q += 256) sq[q] = dec_f(g_mq[b * LQv + q]);
    for (int a = tid; a < LAv; a += 256) sa[a] = dec_f(g_ma[b * LAv + a]);
    __syncthreads();

    if (tid < 32) {
        float m = -1e30f;
        for (int q = lane; q < LQv; q += 32) m = fmaxf(m, sq[q]);
        m = warp_max(m);
        if (lane == 0) smax[0] = m;
    } else if (tid < 64) {
        float m = -1e30f;
        for (int a = lane; a < LAv; a += 32) m = fmaxf(m, sa[a]);
        m = warp_max(m);
        if (lane == 0) smax[1] = m;
    }
    __syncthreads();
    for (int q = tid; q < LQv; q += 256) sq[q] = expf(sq[q] - smax[0]);
    for (int a = tid; a < LAv; a += 256) sa[a] = expf(sa[a] - smax[1]);
    __syncthreads();
    if (tid < 32) {
        float s = 0.0f;
        for (int q = lane; q < LQv; q += 32) s += sq[q];
        s = warp_sum(s);
        if (lane == 0) ssum[0] = s;
    } else if (tid < 64) {
        float s = 0.0f;
        for (int a = lane; a < LAv; a += 32) s += sa[a];
        s = warp_sum(s);
        if (lane == 0) ssum[1] = s;
    }
    __syncthreads();
    float invq = 1.0f / ssum[0], inva = 1.0f / ssum[1];
    for (int q = tid; q < LQv; q += 256)
        g_mq[b * LQv + q] = __float_as_uint(sq[q] * invq);
    for (int a = tid; a < LAv; a += 256)
        g_ma[b * LAv + a] = __float_as_uint(sa[a] * inva);
}

// ---------------------------------------------------------------------------
// 4b) pooling partials: grid (128 b, 2 halves), 256 thr, 200 f each
// ---------------------------------------------------------------------------
__global__ __launch_bounds__(256) void pool_kernel()
{
    __shared__ float wq[LQv], wa[LAv];
    __shared__ float rd[256], rx[256], ry[256];

    const int b = blockIdx.x;
    const int f0 = blockIdx.y * 200;
    const int tid = threadIdx.x;

    for (int q = tid; q < LQv; q += 256) wq[q] = __uint_as_float(g_mq[b * LQv + q]);
    for (int a = tid; a < LAv; a += 256) wa[a] = __uint_as_float(g_ma[b * LAv + a]);
    __syncthreads();

    float d = 0.0f, x = 0.0f, y = 0.0f;
    if (tid < 200) {
        int f = f0 + tid;
        const float* qp = g_Q + (size_t)b * LQv * FILT + f;
        float accq = 0.0f;
#pragma unroll 8
        for (int q = 0; q < LQv; q++) accq += qp[(size_t)q * FILT] * wq[q];
        const float* ap = g_A + (size_t)b * LAv * FILT + f;
        float acca = 0.0f;
#pragma unroll 8
        for (int a = 0; a < LAv; a++) acca += ap[(size_t)a * FILT] * wa[a];
        d = accq * acca; x = accq * accq; y = acca * acca;
    }
    rd[tid] = d; rx[tid] = x; ry[tid] = y;
    __syncthreads();
#pragma unroll
    for (int s = 128; s > 0; s >>= 1) {
        if (tid < s) {
            rd[tid] += rd[tid + s];
            rx[tid] += rx[tid + s];
            ry[tid] += ry[tid + s];
        }
        __syncthreads();
    }
    if (tid == 0) {
        atomicAdd(&g_dxy[b * 4 + 0], rd[0]);
        atomicAdd(&g_dxy[b * 4 + 1], rx[0]);
        atomicAdd(&g_dxy[b * 4 + 2], ry[0]);
    }
}

// ---------------------------------------------------------------------------
// 4c) final cosine
// ---------------------------------------------------------------------------
__global__ __launch_bounds__(128) void final_out_kernel(float* __restrict__ out)
{
    int b = threadIdx.x;
    float D = g_dxy[b * 4 + 0];
    float X = g_dxy[b * 4 + 1];
    float Y = g_dxy[b * 4 + 2];
    float nq = fmaxf(sqrtf(X), 1e-8f);
    float na = fmaxf(sqrtf(Y), 1e-8f);
    out[b] = D / (nq * na);
}

// ---------------------------------------------------------------------------
// launch — two streams: convA on s2 overlaps convQ + gemm_T on main
// ---------------------------------------------------------------------------
extern "C" void kernel_launch(void* const* d_in, const int* in_sizes, int n_in,
                              void* d_out, int out_size)
{
    const int*   questions = (const int*)d_in[0];
    const int*   answers   = (const int*)d_in[1];
    const float* emb       = (const float*)d_in[2];
    const float* conv_w    = (const float*)d_in[3];
    const float* conv_b    = (const float*)d_in[4];
    const float* W         = (const float*)d_in[5];
    float*       out       = (float*)d_out;

    (void)in_sizes; (void)n_in; (void)out_size;

    static bool init_done = false;
    static cudaStream_t s2;
    static cudaEvent_t evFork, evJoin;
    if (!init_done) {
        cudaFuncSetAttribute(conv_encode_kernel,
                             cudaFuncAttributeMaxDynamicSharedMemorySize, SMEM_CONV);
        cudaFuncSetAttribute(gemm_T_kernel,
                             cudaFuncAttributeMaxDynamicSharedMemorySize, SMEM_T);
        cudaFuncSetAttribute(gemm_G_kernel,
                             cudaFuncAttributeMaxDynamicSharedMemorySize, SMEM_G);
        cudaStreamCreateWithFlags(&s2, cudaStreamNonBlocking);
        cudaEventCreateWithFlags(&evFork, cudaEventDisableTiming);
        cudaEventCreateWithFlags(&evJoin, cudaEventDisableTiming);
        init_done = true;
    }

    init_max_kernel<<<(BATCH * LAv + 255) / 256, 256>>>();
    transpose_w_kernel<<<(5 * KCONV * 80 + 255) / 256, 256>>>(conv_w);

    // fork: convA on s2 after transpose
    cudaEventRecord(evFork, 0);
    cudaStreamWaitEvent(s2, evFork, 0);

    conv_encode_kernel<<<dim3(4, 5, BATCH), 128, SMEM_CONV, s2>>>(
        questions, answers, emb, conv_b, 0);   // answers

    // main stream: convQ then T (Q-only dependency)
    conv_encode_kernel<<<dim3(1, 5, BATCH), 128, SMEM_CONV>>>(
        questions, answers, emb, conv_b, 1);   // questions
    gemm_T_kernel<<<dim3(FILT / 80, 1, BATCH), 128, SMEM_T>>>(W);

    // join: G needs A (s2) and T (main)
    cudaEventRecord(evJoin, s2);
    cudaStreamWaitEvent(0, evJoin, 0);

    gemm_G_kernel<<<dim3(LAv / 128, BATCH), 256, SMEM_G>>>();

    softmax_kernel<<<BATCH, 256>>>();
    pool_kernel<<<dim3(BATCH, 2), 256>>>();
    final_out_kernel<<<1, 128>>>(out);
}